// round 10
// baseline (speedup 1.0000x reference)
#include <cuda_runtime.h>
#include <cuda_fp16.h>
#include <cstdint>

#define N_NODES 50000
#define N_EDGES 320000
#define N_E2    370000
#define DIM     256
#define DIN_    128
#define SEQROWS (3*N_NODES)

// ---------------- fp32 scratch ----------------
__device__ float    g_h   [N_NODES*DIM];
__device__ float    g_x1  [N_NODES*DIM];
__device__ float    g_x2  [N_NODES*DIM];
__device__ float    g_ssrc[N_NODES];
__device__ float    g_sdst[N_NODES];
__device__ unsigned g_nmax[N_NODES];
__device__ float    g_den [N_NODES];
__device__ float    g_eex [N_E2];
__device__ float    g_seq [SEQROWS*DIM];

// ---------------- fp16 scratch ----------------
__device__ __half g_hx  [N_NODES*DIN_];
__device__ __half g_hx1 [N_NODES*DIM];
__device__ __half g_hseq[SEQROWS*DIM];
__device__ __half g_hattn[SEQROWS*DIM];
__device__ __half g_hqkv[(size_t)SEQROWS*768];
__device__ __half g_hff [(size_t)SEQROWS*1024];
__device__ __half g_hdelta[SEQROWS*DIM];
// packed half weights
#define OG1  0
#define OG2  (OG1 + 256*128)
#define OQKV (OG2 + 256*256)
#define OWO  (OQKV + 2*768*256)
#define OFF1 (OWO + 2*256*256)
#define OFF2 (OFF1 + 2*1024*256)
#define HWTOT (OFF2 + 2*256*1024)
__device__ __half g_hw[HWTOT];

__device__ __forceinline__ float warp_sum(float v) {
#pragma unroll
    for (int o = 16; o; o >>= 1) v += __shfl_xor_sync(0xffffffffu, v, o);
    return v;
}
__device__ __forceinline__ void red_add4(float* p, float4 v) {
    asm volatile("red.global.add.v4.f32 [%0], {%1, %2, %3, %4};"
                 :: "l"(p), "f"(v.x), "f"(v.y), "f"(v.z), "f"(v.w) : "memory");
}
__device__ __forceinline__ uint32_t smem_u32(const void* p) {
    uint32_t a;
    asm("{ .reg .u64 t; cvta.to.shared.u64 t, %1; cvt.u32.u64 %0, t; }" : "=r"(a) : "l"(p));
    return a;
}
__device__ __forceinline__ uint32_t packh2(float x, float y) {
    uint32_t r;
    asm("cvt.rn.f16x2.f32 %0, %1, %2;" : "=r"(r) : "f"(y), "f"(x));
    return r;
}

// ---------------- f32 -> f16 convert ----------------
__global__ void cvt_f2h(const float* __restrict__ s, __half* __restrict__ d, int n)
{
    const int i = (blockIdx.x * blockDim.x + threadIdx.x) * 4;
    if (i >= n) return;
    float4 v = *(const float4*)(s + i);
    uint32_t* o = (uint32_t*)(d + i);
    o[0] = packh2(v.x, v.y);
    o[1] = packh2(v.z, v.w);
}

// ============== fp16 cp.async GEMM: C[M,Nn] = A[M,K] @ W[Nn,K]^T ==============
// CTA 128x128, BK=64 (128B rows, XOR swizzle), 256 threads, warp tile 64x32.
// CTA raster: groups of 8 M-tiles, N fastest inside a group (L2 reuse of A).
#define TILEB 16384
#define BUFB  (2*TILEB)
#define GSMEM (2*BUFB)              // 65536
#define RASTG 8

__device__ __forceinline__ void cp16(uint32_t s, const void* g) {
    asm volatile("cp.async.cg.shared.global [%0], [%1], 16;" :: "r"(s), "l"(g));
}
__device__ __forceinline__ void ldsm4(uint32_t& r0, uint32_t& r1, uint32_t& r2, uint32_t& r3,
                                      uint32_t addr) {
    asm volatile("ldmatrix.sync.aligned.m8n8.x4.shared.b16 {%0,%1,%2,%3}, [%4];"
                 : "=r"(r0), "=r"(r1), "=r"(r2), "=r"(r3) : "r"(addr));
}
__device__ __forceinline__ void mma_f16(float* c, uint32_t a0, uint32_t a1,
                                        uint32_t a2, uint32_t a3,
                                        uint32_t b0, uint32_t b1) {
    asm volatile(
        "mma.sync.aligned.m16n8k16.row.col.f32.f16.f16.f32 "
        "{%0,%1,%2,%3}, {%4,%5,%6,%7}, {%8,%9}, {%0,%1,%2,%3};"
        : "+f"(c[0]), "+f"(c[1]), "+f"(c[2]), "+f"(c[3])
        : "r"(a0), "r"(a1), "r"(a2), "r"(a3), "r"(b0), "r"(b1));
}

template<bool OUT_HALF, bool BIAS, bool RELU>
__global__ void __launch_bounds__(256, 2) hgemm(
    const __half* __restrict__ A, const __half* __restrict__ W,
    const float* __restrict__ bias, void* __restrict__ Cv,
    int M, int Nn, int K)
{
    extern __shared__ char smraw[];
    const int tid  = threadIdx.x;
    const int lane = tid & 31;
    const int wid  = tid >> 5;
    const int warp_m = wid >> 2;
    const int warp_n = wid & 3;
    const int g  = lane >> 2;
    const int cl = lane & 3;

    // rasterization swizzle
    const int MB = gridDim.x, NB = gridDim.y;
    const int lid = blockIdx.y * MB + blockIdx.x;
    const int grp = lid / (RASTG * NB);
    const int rem = lid - grp * (RASTG * NB);
    const int mstart = grp * RASTG;
    int gsize = MB - mstart; if (gsize > RASTG) gsize = RASTG;
    const int bm0 = (mstart + rem % gsize) * 128;
    const int bn0 = (rem / gsize) * 128;

    const uint32_t smem_byte = smem_u32(smraw);

    float acc[4][4][4];
#pragma unroll
    for (int mi = 0; mi < 4; mi++)
#pragma unroll
        for (int ni = 0; ni < 4; ni++)
#pragma unroll
            for (int c = 0; c < 4; c++) acc[mi][ni][c] = 0.f;

    const int stages = K >> 6;
    const int ld_r = tid >> 3;
    const int ld_c = tid & 7;

    auto issue = [&](int s) {
        const uint32_t abase = smem_byte + (uint32_t)(s & 1) * BUFB;
        const uint32_t bbase = abase + TILEB;
        const int k0 = s << 6;
#pragma unroll
        for (int i = 0; i < 4; i++) {
            const int r = ld_r + 32 * i;
            const uint32_t sw = (uint32_t)((ld_c ^ (r & 7)) << 4);
            int ar = bm0 + r; if (ar > M - 1) ar = M - 1;
            cp16(abase + (uint32_t)r * 128 + sw, A + (size_t)ar * K + k0 + ld_c * 8);
            cp16(bbase + (uint32_t)r * 128 + sw, W + (size_t)(bn0 + r) * K + k0 + ld_c * 8);
        }
        asm volatile("cp.async.commit_group;" ::: "memory");
    };

    issue(0);
    for (int s = 0; s < stages; s++) {
        if (s + 1 < stages) {
            issue(s + 1);
            asm volatile("cp.async.wait_group 1;" ::: "memory");
        } else {
            asm volatile("cp.async.wait_group 0;" ::: "memory");
        }
        __syncthreads();

        const uint32_t Ab = smem_byte + (uint32_t)(s & 1) * BUFB;
        const uint32_t Bb = Ab + TILEB;
        const int row_a = warp_m * 64 + (lane & 15);
        const int ca = lane >> 4;
        const int row_b0 = warp_n * 32 + (lane & 7) + ((lane >> 4) & 1) * 8;
        const int cb = (lane >> 3) & 1;

#pragma unroll
        for (int kq = 0; kq < 4; kq++) {
            const int kb = kq * 2;
            uint32_t afr[4][4];
            uint32_t bfr[4][2];
            const uint32_t sw_a = (uint32_t)(((kb + ca) ^ (lane & 7)) << 4);
#pragma unroll
            for (int mi = 0; mi < 4; mi++)
                ldsm4(afr[mi][0], afr[mi][1], afr[mi][2], afr[mi][3],
                      Ab + (uint32_t)(row_a + mi * 16) * 128 + sw_a);
            const uint32_t sw_b = (uint32_t)(((kb + cb) ^ (lane & 7)) << 4);
#pragma unroll
            for (int p = 0; p < 2; p++)
                ldsm4(bfr[2*p][0], bfr[2*p][1], bfr[2*p+1][0], bfr[2*p+1][1],
                      Bb + (uint32_t)(row_b0 + p * 16) * 128 + sw_b);
#pragma unroll
            for (int mi = 0; mi < 4; mi++)
#pragma unroll
                for (int ni = 0; ni < 4; ni++)
                    mma_f16(acc[mi][ni], afr[mi][0], afr[mi][1], afr[mi][2], afr[mi][3],
                            bfr[ni][0], bfr[ni][1]);
        }
        __syncthreads();
    }

    // epilogue
#pragma unroll
    for (int mi = 0; mi < 4; mi++) {
        const int r0 = bm0 + warp_m * 64 + mi * 16 + g;
#pragma unroll
        for (int ni = 0; ni < 4; ni++) {
            const int col = bn0 + warp_n * 32 + ni * 8 + 2 * cl;
            float bx = 0.f, by = 0.f;
            if (BIAS) { bx = __ldg(bias + col); by = __ldg(bias + col + 1); }
            float2 v0, v1;
            v0.x = acc[mi][ni][0] + bx; v0.y = acc[mi][ni][1] + by;
            v1.x = acc[mi][ni][2] + bx; v1.y = acc[mi][ni][3] + by;
            if (RELU) {
                v0.x = fmaxf(v0.x, 0.f); v0.y = fmaxf(v0.y, 0.f);
                v1.x = fmaxf(v1.x, 0.f); v1.y = fmaxf(v1.y, 0.f);
            }
            if (OUT_HALF) {
                __half* Ch = (__half*)Cv;
                if (r0 < M)     *(uint32_t*)(Ch + (size_t)r0 * Nn + col)       = packh2(v0.x, v0.y);
                if (r0 + 8 < M) *(uint32_t*)(Ch + (size_t)(r0 + 8) * Nn + col) = packh2(v1.x, v1.y);
            } else {
                float* C = (float*)Cv;
                if (r0 < M)     *(float2*)(C + (size_t)r0 * Nn + col)       = v0;
                if (r0 + 8 < M) *(float2*)(C + (size_t)(r0 + 8) * Nn + col) = v1;
            }
        }
    }
}

// ---------------- GAT ----------------
__global__ void gat_scores(const float* __restrict__ h,
                           const float* __restrict__ asrc, const float* __restrict__ adst,
                           float* __restrict__ ssrc, float* __restrict__ sdst)
{
    const int gw = (int)(((size_t)blockIdx.x * blockDim.x + threadIdx.x) >> 5);
    const int lane = threadIdx.x & 31;
    if (gw >= N_NODES) return;
    const float4* hp = (const float4*)(h + (size_t)gw * DIM);
    float s1 = 0.f, s2 = 0.f;
#pragma unroll
    for (int i = 0; i < 2; i++) {
        float4 hv = hp[lane + 32 * i];
        float4 a1 = ((const float4*)asrc)[lane + 32 * i];
        float4 a2 = ((const float4*)adst)[lane + 32 * i];
        s1 += hv.x*a1.x + hv.y*a1.y + hv.z*a1.z + hv.w*a1.w;
        s2 += hv.x*a2.x + hv.y*a2.y + hv.z*a2.z + hv.w*a2.w;
    }
    s1 = warp_sum(s1); s2 = warp_sum(s2);
    if (lane == 0) { ssrc[gw] = s1; sdst[gw] = s2; }
}

__global__ void gat_init(float* __restrict__ acc)
{
    const int idx = blockIdx.x * blockDim.x + threadIdx.x;
    if (idx < N_NODES * DIM) acc[idx] = 0.f;
    if (idx < N_NODES) { g_den[idx] = 0.f; g_nmax[idx] = 0u; }
}

__device__ __forceinline__ unsigned ord_enc(float f) {
    unsigned u = __float_as_uint(f);
    return (u & 0x80000000u) ? ~u : (u | 0x80000000u);
}
__device__ __forceinline__ float ord_dec(unsigned u) {
    return __uint_as_float((u & 0x80000000u) ? (u ^ 0x80000000u) : ~u);
}

__global__ void gat_edge_max(const int* __restrict__ ei,
                             const float* __restrict__ ssrc, const float* __restrict__ sdst,
                             float* __restrict__ e_out, unsigned* __restrict__ nmax)
{
    const int k = blockIdx.x * blockDim.x + threadIdx.x;
    if (k >= N_E2) return;
    const int s = (k < N_EDGES) ? ei[k] : (k - N_EDGES);
    const int d = (k < N_EDGES) ? ei[N_EDGES + k] : (k - N_EDGES);
    float e = ssrc[s] + sdst[d];
    e = (e >= 0.f) ? e : 0.2f * e;
    e_out[k] = e;
    atomicMax(&nmax[d], ord_enc(e));
}

__global__ void gat_edge_exp(const int* __restrict__ ei,
                             float* __restrict__ e_inout,
                             const unsigned* __restrict__ nmax, float* __restrict__ den)
{
    const int k = blockIdx.x * blockDim.x + threadIdx.x;
    if (k >= N_E2) return;
    const int d = (k < N_EDGES) ? ei[N_EDGES + k] : (k - N_EDGES);
    const float m = ord_dec(nmax[d]);
    const float ex = expf(e_inout[k] - m);
    e_inout[k] = ex;
    atomicAdd(&den[d], ex);
}

__global__ void gat_scatter(const int* __restrict__ ei,
                            const float* __restrict__ ex, const float* __restrict__ den,
                            const float* __restrict__ h, float* __restrict__ out)
{
    const int gw = (int)(((size_t)blockIdx.x * blockDim.x + threadIdx.x) >> 5);
    const int lane = threadIdx.x & 31;
    if (gw >= N_E2) return;
    const int s = (gw < N_EDGES) ? ei[gw] : (gw - N_EDGES);
    const int d = (gw < N_EDGES) ? ei[N_EDGES + gw] : (gw - N_EDGES);
    const float alpha = ex[gw] / den[d];
    const float4* hp = (const float4*)(h + (size_t)s * DIM);
    float* op = out + (size_t)d * DIM;
#pragma unroll
    for (int i = 0; i < 2; i++) {
        float4 v = hp[lane + 32 * i];
        v.x *= alpha; v.y *= alpha; v.z *= alpha; v.w *= alpha;
        red_add4(op + (size_t)(lane + 32 * i) * 4, v);
    }
}

template<bool WRITE_H>
__global__ void bias_relu(float* __restrict__ x, const float* __restrict__ b,
                          __half* __restrict__ xh, int total)
{
    const int idx = blockIdx.x * blockDim.x + threadIdx.x;
    if (idx >= total) return;
    const float v = fmaxf(x[idx] + b[idx & (DIM - 1)], 0.f);
    x[idx] = v;
    if (WRITE_H) xh[idx] = __float2half(v);
}

__global__ void build_seq(const float* __restrict__ x1, const float* __restrict__ x2,
                          const float* __restrict__ cls, const float* __restrict__ pos,
                          float* __restrict__ seq, __half* __restrict__ seqh)
{
    const int idx = blockIdx.x * blockDim.x + threadIdx.x;
    if (idx >= N_NODES * DIM) return;
    const int d = idx & (DIM - 1);
    const size_t b = (size_t)(idx >> 8) * 3 * DIM;
    const float v0 = cls[d]  + pos[d];
    const float v1 = x1[idx] + pos[DIM + d];
    const float v2 = x2[idx] + pos[2 * DIM + d];
    seq[b + d] = v0;           seqh[b + d] = __float2half(v0);
    seq[b + DIM + d] = v1;     seqh[b + DIM + d] = __float2half(v1);
    seq[b + 2*DIM + d] = v2;   seqh[b + 2*DIM + d] = __float2half(v2);
}

__global__ void mha_attn(const __half* __restrict__ qkv, __half* __restrict__ o)
{
    const int gw = (int)(((size_t)blockIdx.x * blockDim.x + threadIdx.x) >> 5);
    const int lane = threadIdx.x & 31;
    if (gw >= N_NODES * 4) return;
    const int n = gw >> 2, h = gw & 3;
    const __half* base = qkv + (size_t)n * (3 * 768) + h * 64;
    float q[3][2], k[3][2], v[3][2];
#pragma unroll
    for (int i = 0; i < 3; i++) {
        q[i][0] = __half2float(base[i*768 + lane]);
        q[i][1] = __half2float(base[i*768 + lane + 32]);
        k[i][0] = __half2float(base[i*768 + 256 + lane]);
        k[i][1] = __half2float(base[i*768 + 256 + lane + 32]);
        v[i][0] = __half2float(base[i*768 + 512 + lane]);
        v[i][1] = __half2float(base[i*768 + 512 + lane + 32]);
    }
    float lg[3][3];
#pragma unroll
    for (int i = 0; i < 3; i++)
#pragma unroll
        for (int j = 0; j < 3; j++)
            lg[i][j] = warp_sum(q[i][0]*k[j][0] + q[i][1]*k[j][1]) * 0.125f;
#pragma unroll
    for (int i = 0; i < 3; i++) {
        const float m = fmaxf(lg[i][0], fmaxf(lg[i][1], lg[i][2]));
        const float e0 = expf(lg[i][0] - m), e1 = expf(lg[i][1] - m), e2 = expf(lg[i][2] - m);
        const float inv = 1.f / (e0 + e1 + e2);
        const float a0 = e0 * inv, a1 = e1 * inv, a2 = e2 * inv;
        const float o0 = a0*v[0][0] + a1*v[1][0] + a2*v[2][0];
        const float o1 = a0*v[0][1] + a1*v[1][1] + a2*v[2][1];
        const size_t ob = (size_t)n * 768 + i * 256 + h * 64;
        o[ob + lane]      = __float2half(o0);
        o[ob + lane + 32] = __float2half(o1);
    }
}

// residual(+half delta) + LN
__global__ void ln_res(float* __restrict__ x, const __half* __restrict__ delta,
                       const float* __restrict__ g, const float* __restrict__ b,
                       __half* __restrict__ xh, int rows)
{
    const int row = blockIdx.x * 8 + (threadIdx.x >> 5);
    const int lane = threadIdx.x & 31;
    if (row >= rows) return;
    float4* xp = (float4*)(x + (size_t)row * DIM);
    const uint2* dp = (const uint2*)(delta + (size_t)row * DIM);
    float4 v0 = xp[lane], v1 = xp[lane + 32];
    uint2 du0 = dp[lane], du1 = dp[lane + 32];
    const __half2* dh0 = (const __half2*)&du0;
    const __half2* dh1 = (const __half2*)&du1;
    float2 a0 = __half22float2(dh0[0]), a1 = __half22float2(dh0[1]);
    float2 a2 = __half22float2(dh1[0]), a3 = __half22float2(dh1[1]);
    v0.x += a0.x; v0.y += a0.y; v0.z += a1.x; v0.w += a1.y;
    v1.x += a2.x; v1.y += a2.y; v1.z += a3.x; v1.w += a3.y;
    float s  = v0.x + v0.y + v0.z + v0.w + v1.x + v1.y + v1.z + v1.w;
    float s2 = v0.x*v0.x + v0.y*v0.y + v0.z*v0.z + v0.w*v0.w
             + v1.x*v1.x + v1.y*v1.y + v1.z*v1.z + v1.w*v1.w;
    s = warp_sum(s); s2 = warp_sum(s2);
    const float mean = s * (1.f / DIM);
    const float var  = s2 * (1.f / DIM) - mean * mean;
    const float inv = rsqrtf(var + 1e-5f);
    float4 g0 = ((const float4*)g)[lane], g1 = ((const float4*)g)[lane + 32];
    float4 b0 = ((const float4*)b)[lane], b1 = ((const float4*)b)[lane + 32];
    v0.x = (v0.x - mean) * inv * g0.x + b0.x; v0.y = (v0.y - mean) * inv * g0.y + b0.y;
    v0.z = (v0.z - mean) * inv * g0.z + b0.z; v0.w = (v0.w - mean) * inv * g0.w + b0.w;
    v1.x = (v1.x - mean) * inv * g1.x + b1.x; v1.y = (v1.y - mean) * inv * g1.y + b1.y;
    v1.z = (v1.z - mean) * inv * g1.z + b1.z; v1.w = (v1.w - mean) * inv * g1.w + b1.w;
    xp[lane] = v0; xp[lane + 32] = v1;
    uint2* hp = (uint2*)(xh + (size_t)row * DIM);
    uint2 h0, h1;
    h0.x = packh2(v0.x, v0.y); h0.y = packh2(v0.z, v0.w);
    h1.x = packh2(v1.x, v1.y); h1.y = packh2(v1.z, v1.w);
    hp[lane] = h0; hp[lane + 32] = h1;
}

__global__ void ln_out(const float* __restrict__ seq,
                       const float* __restrict__ g, const float* __restrict__ b,
                       float* __restrict__ out)
{
    const int row = blockIdx.x * 8 + (threadIdx.x >> 5);
    const int lane = threadIdx.x & 31;
    if (row >= N_NODES) return;
    const float4* xp = (const float4*)(seq + (size_t)row * 768);
    float4 v0 = xp[lane], v1 = xp[lane + 32];
    float s  = v0.x + v0.y + v0.z + v0.w + v1.x + v1.y + v1.z + v1.w;
    float s2 = v0.x*v0.x + v0.y*v0.y + v0.z*v0.z + v0.w*v0.w
             + v1.x*v1.x + v1.y*v1.y + v1.z*v1.z + v1.w*v1.w;
    s = warp_sum(s); s2 = warp_sum(s2);
    const float mean = s * (1.f / DIM);
    const float var  = s2 * (1.f / DIM) - mean * mean;
    const float inv = rsqrtf(var + 1e-5f);
    float4 g0 = ((const float4*)g)[lane], g1 = ((const float4*)g)[lane + 32];
    float4 b0 = ((const float4*)b)[lane], b1 = ((const float4*)b)[lane + 32];
    v0.x = (v0.x - mean) * inv * g0.x + b0.x; v0.y = (v0.y - mean) * inv * g0.y + b0.y;
    v0.z = (v0.z - mean) * inv * g0.z + b0.z; v0.w = (v0.w - mean) * inv * g0.w + b0.w;
    v1.x = (v1.x - mean) * inv * g1.x + b1.x; v1.y = (v1.y - mean) * inv * g1.y + b1.y;
    v1.z = (v1.z - mean) * inv * g1.z + b1.z; v1.w = (v1.w - mean) * inv * g1.w + b1.w;
    float4* op = (float4*)(out + (size_t)row * DIM);
    op[lane] = v0; op[lane + 32] = v1;
}

// ---------------- host ----------------
static void* symaddr(const void* sym) {
    void* p = nullptr;
    cudaGetSymbolAddress(&p, sym);
    return p;
}

template<bool OUT_HALF, bool BIAS, bool RELU>
static void launch_gemm(const __half* A, const __half* W, const float* bias, void* C,
                        int M, int Nn, int K)
{
    cudaFuncSetAttribute(hgemm<OUT_HALF, BIAS, RELU>,
                         cudaFuncAttributeMaxDynamicSharedMemorySize, GSMEM);
    dim3 grid((M + 127) / 128, Nn / 128);
    hgemm<OUT_HALF, BIAS, RELU><<<grid, 256, GSMEM>>>(A, W, bias, C, M, Nn, K);
}

static void cvt(const float* s, __half* d, int n) {
    cvt_f2h<<<(n / 4 + 255) / 256, 256>>>(s, d, n);
}

extern "C" void kernel_launch(void* const* d_in, const int* in_sizes, int n_in,
                              void* d_out, int out_size)
{
    (void)in_sizes; (void)n_in; (void)out_size;
    const float* x         = (const float*)d_in[0];
    const int*   ei        = (const int*)  d_in[1];
    const float* gat1_W    = (const float*)d_in[2];
    const float* gat1_b    = (const float*)d_in[3];
    const float* gat1_asrc = (const float*)d_in[4];
    const float* gat1_adst = (const float*)d_in[5];
    const float* gat2_W    = (const float*)d_in[6];
    const float* gat2_b    = (const float*)d_in[7];
    const float* gat2_asrc = (const float*)d_in[8];
    const float* gat2_adst = (const float*)d_in[9];
    const float* cls       = (const float*)d_in[10];
    const float* pos       = (const float*)d_in[11];
    const float* Wqkv      = (const float*)d_in[12];
    const float* bqkv      = (const float*)d_in[13];
    const float* Wo        = (const float*)d_in[14];
    const float* bo        = (const float*)d_in[15];
    const float* ln1_g     = (const float*)d_in[16];
    const float* ln1_b     = (const float*)d_in[17];
    const float* ln2_g     = (const float*)d_in[18];
    const float* ln2_b     = (const float*)d_in[19];
    const float* Wff1      = (const float*)d_in[20];
    const float* bff1      = (const float*)d_in[21];
    const float* Wff2      = (const float*)d_in[22];
    const float* bff2      = (const float*)d_in[23];
    const float* norm_g    = (const float*)d_in[24];
    const float* norm_b    = (const float*)d_in[25];
    float* out = (float*)d_out;

    float*    p_h    = (float*)symaddr(g_h);
    float*    p_x1   = (float*)symaddr(g_x1);
    float*    p_x2   = (float*)symaddr(g_x2);
    float*    p_ssrc = (float*)symaddr(g_ssrc);
    float*    p_sdst = (float*)symaddr(g_sdst);
    unsigned* p_nmax = (unsigned*)symaddr(g_nmax);
    float*    p_den  = (float*)symaddr(g_den);
    float*    p_eex  = (float*)symaddr(g_eex);
    float*    p_seq  = (float*)symaddr(g_seq);
    __half*   p_hx   = (__half*)symaddr(g_hx);
    __half*   p_hx1  = (__half*)symaddr(g_hx1);
    __half*   p_hseq = (__half*)symaddr(g_hseq);
    __half*   p_hattn= (__half*)symaddr(g_hattn);
    __half*   p_hqkv = (__half*)symaddr(g_hqkv);
    __half*   p_hff  = (__half*)symaddr(g_hff);
    __half*   p_hdel = (__half*)symaddr(g_hdelta);
    __half*   p_hw   = (__half*)symaddr(g_hw);

    // ---- one-time converts ----
    cvt(x, p_hx, N_NODES * DIN_);
    cvt(gat1_W, p_hw + OG1, 256 * 128);
    cvt(gat2_W, p_hw + OG2, 256 * 256);
    cvt(Wqkv,   p_hw + OQKV, 2 * 768 * 256);
    cvt(Wo,     p_hw + OWO,  2 * 256 * 256);
    cvt(Wff1,   p_hw + OFF1, 2 * 1024 * 256);
    cvt(Wff2,   p_hw + OFF2, 2 * 256 * 1024);

    const int TB = 256;
    const int nwb_nodes = (N_NODES * 32 + TB - 1) / TB;
    const int blk_nd    = (N_NODES * DIM + TB - 1) / TB;
    const int blk_e     = (N_E2 + TB - 1) / TB;
    const int nwb_edges = ((size_t)N_E2 * 32 + TB - 1) / TB;

    // ---- GAT layer 1 ----
    launch_gemm<false, false, false>(p_hx, p_hw + OG1, nullptr, p_h, N_NODES, DIM, DIN_);
    gat_scores<<<nwb_nodes, TB>>>(p_h, gat1_asrc, gat1_adst, p_ssrc, p_sdst);
    gat_init<<<blk_nd, TB>>>(p_x1);
    gat_edge_max<<<blk_e, TB>>>(ei, p_ssrc, p_sdst, p_eex, p_nmax);
    gat_edge_exp<<<blk_e, TB>>>(ei, p_eex, p_nmax, p_den);
    gat_scatter<<<nwb_edges, TB>>>(ei, p_eex, p_den, p_h, p_x1);
    bias_relu<true><<<blk_nd, TB>>>(p_x1, gat1_b, p_hx1, N_NODES * DIM);

    // ---- GAT layer 2 ----
    launch_gemm<false, false, false>(p_hx1, p_hw + OG2, nullptr, p_h, N_NODES, DIM, DIM);
    gat_scores<<<nwb_nodes, TB>>>(p_h, gat2_asrc, gat2_adst, p_ssrc, p_sdst);
    gat_init<<<blk_nd, TB>>>(p_x2);
    gat_edge_max<<<blk_e, TB>>>(ei, p_ssrc, p_sdst, p_eex, p_nmax);
    gat_edge_exp<<<blk_e, TB>>>(ei, p_eex, p_nmax, p_den);
    gat_scatter<<<nwb_edges, TB>>>(ei, p_eex, p_den, p_h, p_x2);
    bias_relu<false><<<blk_nd, TB>>>(p_x2, gat2_b, nullptr, N_NODES * DIM);

    // ---- sequence ----
    build_seq<<<blk_nd, TB>>>(p_x1, p_x2, cls, pos, p_seq, p_hseq);

    // ---- transformer ----
    const int nwb_attn = (N_NODES * 4 * 32 + TB - 1) / TB;
    const int blk_ln   = (SEQROWS + 7) / 8;

    for (int l = 0; l < 2; l++) {
        const __half* Wq   = p_hw + OQKV + (size_t)l * 768 * 256;
        const float*  bq   = bqkv + (size_t)l * 768;
        const __half* Wo_l = p_hw + OWO + (size_t)l * 256 * 256;
        const float*  bo_l = bo + (size_t)l * 256;
        const __half* W1   = p_hw + OFF1 + (size_t)l * 1024 * 256;
        const float*  b1   = bff1 + (size_t)l * 1024;
        const __half* W2   = p_hw + OFF2 + (size_t)l * 256 * 1024;
        const float*  b2   = bff2 + (size_t)l * 256;

        launch_gemm<true, true, false>(p_hseq, Wq, bq, p_hqkv, SEQROWS, 768, 256);
        mha_attn<<<nwb_attn, TB>>>(p_hqkv, p_hattn);
        launch_gemm<true, true, false>(p_hattn, Wo_l, bo_l, p_hdel, SEQROWS, 256, 256);
        ln_res<<<blk_ln, TB>>>(p_seq, p_hdel, ln1_g + l * 256, ln1_b + l * 256, p_hseq, SEQROWS);
        launch_gemm<true, true, true>(p_hseq, W1, b1, p_hff, SEQROWS, 1024, 256);
        launch_gemm<true, true, false>(p_hff, W2, b2, p_hdel, SEQROWS, 256, 1024);
        ln_res<<<blk_ln, TB>>>(p_seq, p_hdel, ln2_g + l * 256, ln2_b + l * 256, p_hseq, SEQROWS);
    }

    ln_out<<<(N_NODES + 7) / 8, TB>>>(p_seq, norm_g, norm_b, out);
}

// round 11
// speedup vs baseline: 1.0144x; 1.0144x over previous
#include <cuda_runtime.h>
#include <cuda_fp16.h>
#include <cstdint>

#define N_NODES 50000
#define N_EDGES 320000
#define N_E2    370000
#define DIM     256
#define DIN_    128
#define SEQROWS (3*N_NODES)

// ---------------- fp32 scratch ----------------
__device__ float    g_h   [N_NODES*DIM];
__device__ float    g_x1  [N_NODES*DIM];
__device__ float    g_x2  [N_NODES*DIM];
__device__ float    g_ssrc[N_NODES];
__device__ float    g_sdst[N_NODES];
__device__ unsigned g_nmax[N_NODES];
__device__ float    g_den [N_NODES];
__device__ float    g_eex [N_E2];
__device__ float    g_seq [SEQROWS*DIM];

// ---------------- fp16 scratch ----------------
__device__ __half g_hx  [N_NODES*DIN_];
__device__ __half g_hx1 [N_NODES*DIM];
__device__ __half g_hseq[SEQROWS*DIM];
__device__ __half g_hattn[SEQROWS*DIM];
__device__ __half g_hqkv[(size_t)SEQROWS*768];
__device__ __half g_hff [(size_t)SEQROWS*1024];
__device__ __half g_hdelta[SEQROWS*DIM];
// packed half weights
#define OG1  0
#define OG2  (OG1 + 256*128)
#define OQKV (OG2 + 256*256)
#define OWO  (OQKV + 2*768*256)
#define OFF1 (OWO + 2*256*256)
#define OFF2 (OFF1 + 2*1024*256)
#define HWTOT (OFF2 + 2*256*1024)
__device__ __half g_hw[HWTOT];

__device__ __forceinline__ float warp_sum(float v) {
#pragma unroll
    for (int o = 16; o; o >>= 1) v += __shfl_xor_sync(0xffffffffu, v, o);
    return v;
}
__device__ __forceinline__ void red_add4(float* p, float4 v) {
    asm volatile("red.global.add.v4.f32 [%0], {%1, %2, %3, %4};"
                 :: "l"(p), "f"(v.x), "f"(v.y), "f"(v.z), "f"(v.w) : "memory");
}
__device__ __forceinline__ uint32_t smem_u32(const void* p) {
    uint32_t a;
    asm("{ .reg .u64 t; cvta.to.shared.u64 t, %1; cvt.u32.u64 %0, t; }" : "=r"(a) : "l"(p));
    return a;
}
__device__ __forceinline__ uint32_t packh2(float x, float y) {
    uint32_t r;
    asm("cvt.rn.f16x2.f32 %0, %1, %2;" : "=r"(r) : "f"(y), "f"(x));
    return r;
}

// ---------------- f32 -> f16 convert ----------------
__global__ void cvt_f2h(const float* __restrict__ s, __half* __restrict__ d, int n)
{
    const int i = (blockIdx.x * blockDim.x + threadIdx.x) * 4;
    if (i >= n) return;
    float4 v = *(const float4*)(s + i);
    uint32_t* o = (uint32_t*)(d + i);
    o[0] = packh2(v.x, v.y);
    o[1] = packh2(v.z, v.w);
}

// ============== fp16 cp.async GEMM: C[M,Nn] = A[M,K] @ W[Nn,K]^T ==============
// CTA 128x128, BK=64 (128B rows, XOR swizzle), 256 threads, warp tile 64x32.
#define TILEB 16384
#define BUFB  (2*TILEB)
#define GSMEM (2*BUFB)              // 65536

__device__ __forceinline__ void cp16(uint32_t s, const void* g) {
    asm volatile("cp.async.cg.shared.global [%0], [%1], 16;" :: "r"(s), "l"(g));
}
__device__ __forceinline__ void ldsm4(uint32_t& r0, uint32_t& r1, uint32_t& r2, uint32_t& r3,
                                      uint32_t addr) {
    asm volatile("ldmatrix.sync.aligned.m8n8.x4.shared.b16 {%0,%1,%2,%3}, [%4];"
                 : "=r"(r0), "=r"(r1), "=r"(r2), "=r"(r3) : "r"(addr));
}
__device__ __forceinline__ void mma_f16(float* c, uint32_t a0, uint32_t a1,
                                        uint32_t a2, uint32_t a3,
                                        uint32_t b0, uint32_t b1) {
    asm volatile(
        "mma.sync.aligned.m16n8k16.row.col.f32.f16.f16.f32 "
        "{%0,%1,%2,%3}, {%4,%5,%6,%7}, {%8,%9}, {%0,%1,%2,%3};"
        : "+f"(c[0]), "+f"(c[1]), "+f"(c[2]), "+f"(c[3])
        : "r"(a0), "r"(a1), "r"(a2), "r"(a3), "r"(b0), "r"(b1));
}

template<bool OUT_HALF, bool BIAS, bool RELU>
__global__ void __launch_bounds__(256, 2) hgemm(
    const __half* __restrict__ A, const __half* __restrict__ W,
    const float* __restrict__ bias, void* __restrict__ Cv,
    int M, int Nn, int K)
{
    extern __shared__ char smraw[];
    const int tid  = threadIdx.x;
    const int lane = tid & 31;
    const int wid  = tid >> 5;
    const int warp_m = wid >> 2;
    const int warp_n = wid & 3;
    const int g  = lane >> 2;
    const int cl = lane & 3;
    const int bm0 = blockIdx.x * 128;
    const int bn0 = blockIdx.y * 128;
    const uint32_t smem_byte = smem_u32(smraw);

    float acc[4][4][4];
#pragma unroll
    for (int mi = 0; mi < 4; mi++)
#pragma unroll
        for (int ni = 0; ni < 4; ni++)
#pragma unroll
            for (int c = 0; c < 4; c++) acc[mi][ni][c] = 0.f;

    const int stages = K >> 6;
    const int ld_r = tid >> 3;
    const int ld_c = tid & 7;

    auto issue = [&](int s) {
        const uint32_t abase = smem_byte + (uint32_t)(s & 1) * BUFB;
        const uint32_t bbase = abase + TILEB;
        const int k0 = s << 6;
#pragma unroll
        for (int i = 0; i < 4; i++) {
            const int r = ld_r + 32 * i;
            const uint32_t sw = (uint32_t)((ld_c ^ (r & 7)) << 4);
            int ar = bm0 + r; if (ar > M - 1) ar = M - 1;
            cp16(abase + (uint32_t)r * 128 + sw, A + (size_t)ar * K + k0 + ld_c * 8);
            cp16(bbase + (uint32_t)r * 128 + sw, W + (size_t)(bn0 + r) * K + k0 + ld_c * 8);
        }
        asm volatile("cp.async.commit_group;" ::: "memory");
    };

    issue(0);
    for (int s = 0; s < stages; s++) {
        if (s + 1 < stages) {
            issue(s + 1);
            asm volatile("cp.async.wait_group 1;" ::: "memory");
        } else {
            asm volatile("cp.async.wait_group 0;" ::: "memory");
        }
        __syncthreads();

        const uint32_t Ab = smem_byte + (uint32_t)(s & 1) * BUFB;
        const uint32_t Bb = Ab + TILEB;
        const int row_a = warp_m * 64 + (lane & 15);
        const int ca = lane >> 4;
        const int row_b0 = warp_n * 32 + (lane & 7) + ((lane >> 4) & 1) * 8;
        const int cb = (lane >> 3) & 1;

#pragma unroll
        for (int kq = 0; kq < 4; kq++) {
            const int kb = kq * 2;
            uint32_t afr[4][4];
            uint32_t bfr[4][2];
            const uint32_t sw_a = (uint32_t)(((kb + ca) ^ (lane & 7)) << 4);
#pragma unroll
            for (int mi = 0; mi < 4; mi++)
                ldsm4(afr[mi][0], afr[mi][1], afr[mi][2], afr[mi][3],
                      Ab + (uint32_t)(row_a + mi * 16) * 128 + sw_a);
            const uint32_t sw_b = (uint32_t)(((kb + cb) ^ (lane & 7)) << 4);
#pragma unroll
            for (int p = 0; p < 2; p++)
                ldsm4(bfr[2*p][0], bfr[2*p][1], bfr[2*p+1][0], bfr[2*p+1][1],
                      Bb + (uint32_t)(row_b0 + p * 16) * 128 + sw_b);
#pragma unroll
            for (int mi = 0; mi < 4; mi++)
#pragma unroll
                for (int ni = 0; ni < 4; ni++)
                    mma_f16(acc[mi][ni], afr[mi][0], afr[mi][1], afr[mi][2], afr[mi][3],
                            bfr[ni][0], bfr[ni][1]);
        }
        __syncthreads();
    }

    // epilogue
#pragma unroll
    for (int mi = 0; mi < 4; mi++) {
        const int r0 = bm0 + warp_m * 64 + mi * 16 + g;
#pragma unroll
        for (int ni = 0; ni < 4; ni++) {
            const int col = bn0 + warp_n * 32 + ni * 8 + 2 * cl;
            float bx = 0.f, by = 0.f;
            if (BIAS) { bx = __ldg(bias + col); by = __ldg(bias + col + 1); }
            float2 v0, v1;
            v0.x = acc[mi][ni][0] + bx; v0.y = acc[mi][ni][1] + by;
            v1.x = acc[mi][ni][2] + bx; v1.y = acc[mi][ni][3] + by;
            if (RELU) {
                v0.x = fmaxf(v0.x, 0.f); v0.y = fmaxf(v0.y, 0.f);
                v1.x = fmaxf(v1.x, 0.f); v1.y = fmaxf(v1.y, 0.f);
            }
            if (OUT_HALF) {
                __half* Ch = (__half*)Cv;
                if (r0 < M)     *(uint32_t*)(Ch + (size_t)r0 * Nn + col)       = packh2(v0.x, v0.y);
                if (r0 + 8 < M) *(uint32_t*)(Ch + (size_t)(r0 + 8) * Nn + col) = packh2(v1.x, v1.y);
            } else {
                float* C = (float*)Cv;
                if (r0 < M)     *(float2*)(C + (size_t)r0 * Nn + col)       = v0;
                if (r0 + 8 < M) *(float2*)(C + (size_t)(r0 + 8) * Nn + col) = v1;
            }
        }
    }
}

// ---------------- GAT ----------------
__global__ void gat_scores(const float* __restrict__ h,
                           const float* __restrict__ asrc, const float* __restrict__ adst,
                           float* __restrict__ ssrc, float* __restrict__ sdst)
{
    const int gw = (int)(((size_t)blockIdx.x * blockDim.x + threadIdx.x) >> 5);
    const int lane = threadIdx.x & 31;
    if (gw >= N_NODES) return;
    const float4* hp = (const float4*)(h + (size_t)gw * DIM);
    float s1 = 0.f, s2 = 0.f;
#pragma unroll
    for (int i = 0; i < 2; i++) {
        float4 hv = hp[lane + 32 * i];
        float4 a1 = ((const float4*)asrc)[lane + 32 * i];
        float4 a2 = ((const float4*)adst)[lane + 32 * i];
        s1 += hv.x*a1.x + hv.y*a1.y + hv.z*a1.z + hv.w*a1.w;
        s2 += hv.x*a2.x + hv.y*a2.y + hv.z*a2.z + hv.w*a2.w;
    }
    s1 = warp_sum(s1); s2 = warp_sum(s2);
    if (lane == 0) { ssrc[gw] = s1; sdst[gw] = s2; }
}

__global__ void gat_init(float* __restrict__ acc)
{
    const int idx = blockIdx.x * blockDim.x + threadIdx.x;
    if (idx < N_NODES * DIM) acc[idx] = 0.f;
    if (idx < N_NODES) { g_den[idx] = 0.f; g_nmax[idx] = 0u; }
}

__device__ __forceinline__ unsigned ord_enc(float f) {
    unsigned u = __float_as_uint(f);
    return (u & 0x80000000u) ? ~u : (u | 0x80000000u);
}
__device__ __forceinline__ float ord_dec(unsigned u) {
    return __uint_as_float((u & 0x80000000u) ? (u ^ 0x80000000u) : ~u);
}

__global__ void gat_edge_max(const int* __restrict__ ei,
                             const float* __restrict__ ssrc, const float* __restrict__ sdst,
                             float* __restrict__ e_out, unsigned* __restrict__ nmax)
{
    const int k = blockIdx.x * blockDim.x + threadIdx.x;
    if (k >= N_E2) return;
    const int s = (k < N_EDGES) ? ei[k] : (k - N_EDGES);
    const int d = (k < N_EDGES) ? ei[N_EDGES + k] : (k - N_EDGES);
    float e = ssrc[s] + sdst[d];
    e = (e >= 0.f) ? e : 0.2f * e;
    e_out[k] = e;
    atomicMax(&nmax[d], ord_enc(e));
}

__global__ void gat_edge_exp(const int* __restrict__ ei,
                             float* __restrict__ e_inout,
                             const unsigned* __restrict__ nmax, float* __restrict__ den)
{
    const int k = blockIdx.x * blockDim.x + threadIdx.x;
    if (k >= N_E2) return;
    const int d = (k < N_EDGES) ? ei[N_EDGES + k] : (k - N_EDGES);
    const float m = ord_dec(nmax[d]);
    const float ex = expf(e_inout[k] - m);
    e_inout[k] = ex;
    atomicAdd(&den[d], ex);
}

__global__ void gat_scatter(const int* __restrict__ ei,
                            const float* __restrict__ ex, const float* __restrict__ den,
                            const float* __restrict__ h, float* __restrict__ out)
{
    const int gw = (int)(((size_t)blockIdx.x * blockDim.x + threadIdx.x) >> 5);
    const int lane = threadIdx.x & 31;
    if (gw >= N_E2) return;
    const int s = (gw < N_EDGES) ? ei[gw] : (gw - N_EDGES);
    const int d = (gw < N_EDGES) ? ei[N_EDGES + gw] : (gw - N_EDGES);
    const float alpha = ex[gw] / den[d];
    const float4* hp = (const float4*)(h + (size_t)s * DIM);
    float* op = out + (size_t)d * DIM;
#pragma unroll
    for (int i = 0; i < 2; i++) {
        float4 v = hp[lane + 32 * i];
        v.x *= alpha; v.y *= alpha; v.z *= alpha; v.w *= alpha;
        red_add4(op + (size_t)(lane + 32 * i) * 4, v);
    }
}

template<bool WRITE_H>
__global__ void bias_relu(float* __restrict__ x, const float* __restrict__ b,
                          __half* __restrict__ xh, int total)
{
    const int idx = blockIdx.x * blockDim.x + threadIdx.x;
    if (idx >= total) return;
    const float v = fmaxf(x[idx] + b[idx & (DIM - 1)], 0.f);
    x[idx] = v;
    if (WRITE_H) xh[idx] = __float2half(v);
}

__global__ void build_seq(const float* __restrict__ x1, const float* __restrict__ x2,
                          const float* __restrict__ cls, const float* __restrict__ pos,
                          float* __restrict__ seq, __half* __restrict__ seqh)
{
    const int idx = blockIdx.x * blockDim.x + threadIdx.x;
    if (idx >= N_NODES * DIM) return;
    const int d = idx & (DIM - 1);
    const size_t b = (size_t)(idx >> 8) * 3 * DIM;
    const float v0 = cls[d]  + pos[d];
    const float v1 = x1[idx] + pos[DIM + d];
    const float v2 = x2[idx] + pos[2 * DIM + d];
    seq[b + d] = v0;           seqh[b + d] = __float2half(v0);
    seq[b + DIM + d] = v1;     seqh[b + DIM + d] = __float2half(v1);
    seq[b + 2*DIM + d] = v2;   seqh[b + 2*DIM + d] = __float2half(v2);
}

__global__ void mha_attn(const __half* __restrict__ qkv, __half* __restrict__ o)
{
    const int gw = (int)(((size_t)blockIdx.x * blockDim.x + threadIdx.x) >> 5);
    const int lane = threadIdx.x & 31;
    if (gw >= N_NODES * 4) return;
    const int n = gw >> 2, h = gw & 3;
    const __half* base = qkv + (size_t)n * (3 * 768) + h * 64;
    float q[3][2], k[3][2], v[3][2];
#pragma unroll
    for (int i = 0; i < 3; i++) {
        q[i][0] = __half2float(base[i*768 + lane]);
        q[i][1] = __half2float(base[i*768 + lane + 32]);
        k[i][0] = __half2float(base[i*768 + 256 + lane]);
        k[i][1] = __half2float(base[i*768 + 256 + lane + 32]);
        v[i][0] = __half2float(base[i*768 + 512 + lane]);
        v[i][1] = __half2float(base[i*768 + 512 + lane + 32]);
    }
    float lg[3][3];
#pragma unroll
    for (int i = 0; i < 3; i++)
#pragma unroll
        for (int j = 0; j < 3; j++)
            lg[i][j] = warp_sum(q[i][0]*k[j][0] + q[i][1]*k[j][1]) * 0.125f;
#pragma unroll
    for (int i = 0; i < 3; i++) {
        const float m = fmaxf(lg[i][0], fmaxf(lg[i][1], lg[i][2]));
        const float e0 = expf(lg[i][0] - m), e1 = expf(lg[i][1] - m), e2 = expf(lg[i][2] - m);
        const float inv = 1.f / (e0 + e1 + e2);
        const float a0 = e0 * inv, a1 = e1 * inv, a2 = e2 * inv;
        const float o0 = a0*v[0][0] + a1*v[1][0] + a2*v[2][0];
        const float o1 = a0*v[0][1] + a1*v[1][1] + a2*v[2][1];
        const size_t ob = (size_t)n * 768 + i * 256 + h * 64;
        o[ob + lane]      = __float2half(o0);
        o[ob + lane + 32] = __float2half(o1);
    }
}

// residual(+half delta) + LN
__global__ void ln_res(float* __restrict__ x, const __half* __restrict__ delta,
                       const float* __restrict__ g, const float* __restrict__ b,
                       __half* __restrict__ xh, int rows)
{
    const int row = blockIdx.x * 8 + (threadIdx.x >> 5);
    const int lane = threadIdx.x & 31;
    if (row >= rows) return;
    float4* xp = (float4*)(x + (size_t)row * DIM);
    const uint2* dp = (const uint2*)(delta + (size_t)row * DIM);
    float4 v0 = xp[lane], v1 = xp[lane + 32];
    uint2 du0 = dp[lane], du1 = dp[lane + 32];
    const __half2* dh0 = (const __half2*)&du0;
    const __half2* dh1 = (const __half2*)&du1;
    float2 a0 = __half22float2(dh0[0]), a1 = __half22float2(dh0[1]);
    float2 a2 = __half22float2(dh1[0]), a3 = __half22float2(dh1[1]);
    v0.x += a0.x; v0.y += a0.y; v0.z += a1.x; v0.w += a1.y;
    v1.x += a2.x; v1.y += a2.y; v1.z += a3.x; v1.w += a3.y;
    float s  = v0.x + v0.y + v0.z + v0.w + v1.x + v1.y + v1.z + v1.w;
    float s2 = v0.x*v0.x + v0.y*v0.y + v0.z*v0.z + v0.w*v0.w
             + v1.x*v1.x + v1.y*v1.y + v1.z*v1.z + v1.w*v1.w;
    s = warp_sum(s); s2 = warp_sum(s2);
    const float mean = s * (1.f / DIM);
    const float var  = s2 * (1.f / DIM) - mean * mean;
    const float inv = rsqrtf(var + 1e-5f);
    float4 g0 = ((const float4*)g)[lane], g1 = ((const float4*)g)[lane + 32];
    float4 b0 = ((const float4*)b)[lane], b1 = ((const float4*)b)[lane + 32];
    v0.x = (v0.x - mean) * inv * g0.x + b0.x; v0.y = (v0.y - mean) * inv * g0.y + b0.y;
    v0.z = (v0.z - mean) * inv * g0.z + b0.z; v0.w = (v0.w - mean) * inv * g0.w + b0.w;
    v1.x = (v1.x - mean) * inv * g1.x + b1.x; v1.y = (v1.y - mean) * inv * g1.y + b1.y;
    v1.z = (v1.z - mean) * inv * g1.z + b1.z; v1.w = (v1.w - mean) * inv * g1.w + b1.w;
    xp[lane] = v0; xp[lane + 32] = v1;
    uint2* hp = (uint2*)(xh + (size_t)row * DIM);
    uint2 h0, h1;
    h0.x = packh2(v0.x, v0.y); h0.y = packh2(v0.z, v0.w);
    h1.x = packh2(v1.x, v1.y); h1.y = packh2(v1.z, v1.w);
    hp[lane] = h0; hp[lane + 32] = h1;
}

__global__ void ln_out(const float* __restrict__ seq,
                       const float* __restrict__ g, const float* __restrict__ b,
                       float* __restrict__ out)
{
    const int row = blockIdx.x * 8 + (threadIdx.x >> 5);
    const int lane = threadIdx.x & 31;
    if (row >= N_NODES) return;
    const float4* xp = (const float4*)(seq + (size_t)row * 768);
    float4 v0 = xp[lane], v1 = xp[lane + 32];
    float s  = v0.x + v0.y + v0.z + v0.w + v1.x + v1.y + v1.z + v1.w;
    float s2 = v0.x*v0.x + v0.y*v0.y + v0.z*v0.z + v0.w*v0.w
             + v1.x*v1.x + v1.y*v1.y + v1.z*v1.z + v1.w*v1.w;
    s = warp_sum(s); s2 = warp_sum(s2);
    const float mean = s * (1.f / DIM);
    const float var  = s2 * (1.f / DIM) - mean * mean;
    const float inv = rsqrtf(var + 1e-5f);
    float4 g0 = ((const float4*)g)[lane], g1 = ((const float4*)g)[lane + 32];
    float4 b0 = ((const float4*)b)[lane], b1 = ((const float4*)b)[lane + 32];
    v0.x = (v0.x - mean) * inv * g0.x + b0.x; v0.y = (v0.y - mean) * inv * g0.y + b0.y;
    v0.z = (v0.z - mean) * inv * g0.z + b0.z; v0.w = (v0.w - mean) * inv * g0.w + b0.w;
    v1.x = (v1.x - mean) * inv * g1.x + b1.x; v1.y = (v1.y - mean) * inv * g1.y + b1.y;
    v1.z = (v1.z - mean) * inv * g1.z + b1.z; v1.w = (v1.w - mean) * inv * g1.w + b1.w;
    float4* op = (float4*)(out + (size_t)row * DIM);
    op[lane] = v0; op[lane + 32] = v1;
}

// ---------------- host ----------------
static void* symaddr(const void* sym) {
    void* p = nullptr;
    cudaGetSymbolAddress(&p, sym);
    return p;
}

template<bool OUT_HALF, bool BIAS, bool RELU>
static void launch_gemm(const __half* A, const __half* W, const float* bias, void* C,
                        int M, int Nn, int K)
{
    cudaFuncSetAttribute(hgemm<OUT_HALF, BIAS, RELU>,
                         cudaFuncAttributeMaxDynamicSharedMemorySize, GSMEM);
    dim3 grid((M + 127) / 128, Nn / 128);
    hgemm<OUT_HALF, BIAS, RELU><<<grid, 256, GSMEM>>>(A, W, bias, C, M, Nn, K);
}

static void cvt(const float* s, __half* d, int n) {
    cvt_f2h<<<(n / 4 + 255) / 256, 256>>>(s, d, n);
}

extern "C" void kernel_launch(void* const* d_in, const int* in_sizes, int n_in,
                              void* d_out, int out_size)
{
    (void)in_sizes; (void)n_in; (void)out_size;
    const float* x         = (const float*)d_in[0];
    const int*   ei        = (const int*)  d_in[1];
    const float* gat1_W    = (const float*)d_in[2];
    const float* gat1_b    = (const float*)d_in[3];
    const float* gat1_asrc = (const float*)d_in[4];
    const float* gat1_adst = (const float*)d_in[5];
    const float* gat2_W    = (const float*)d_in[6];
    const float* gat2_b    = (const float*)d_in[7];
    const float* gat2_asrc = (const float*)d_in[8];
    const float* gat2_adst = (const float*)d_in[9];
    const float* cls       = (const float*)d_in[10];
    const float* pos       = (const float*)d_in[11];
    const float* Wqkv      = (const float*)d_in[12];
    const float* bqkv      = (const float*)d_in[13];
    const float* Wo        = (const float*)d_in[14];
    const float* bo        = (const float*)d_in[15];
    const float* ln1_g     = (const float*)d_in[16];
    const float* ln1_b     = (const float*)d_in[17];
    const float* ln2_g     = (const float*)d_in[18];
    const float* ln2_b     = (const float*)d_in[19];
    const float* Wff1      = (const float*)d_in[20];
    const float* bff1      = (const float*)d_in[21];
    const float* Wff2      = (const float*)d_in[22];
    const float* bff2      = (const float*)d_in[23];
    const float* norm_g    = (const float*)d_in[24];
    const float* norm_b    = (const float*)d_in[25];
    float* out = (float*)d_out;

    float*    p_h    = (float*)symaddr(g_h);
    float*    p_x1   = (float*)symaddr(g_x1);
    float*    p_x2   = (float*)symaddr(g_x2);
    float*    p_ssrc = (float*)symaddr(g_ssrc);
    float*    p_sdst = (float*)symaddr(g_sdst);
    unsigned* p_nmax = (unsigned*)symaddr(g_nmax);
    float*    p_den  = (float*)symaddr(g_den);
    float*    p_eex  = (float*)symaddr(g_eex);
    float*    p_seq  = (float*)symaddr(g_seq);
    __half*   p_hx   = (__half*)symaddr(g_hx);
    __half*   p_hx1  = (__half*)symaddr(g_hx1);
    __half*   p_hseq = (__half*)symaddr(g_hseq);
    __half*   p_hattn= (__half*)symaddr(g_hattn);
    __half*   p_hqkv = (__half*)symaddr(g_hqkv);
    __half*   p_hff  = (__half*)symaddr(g_hff);
    __half*   p_hdel = (__half*)symaddr(g_hdelta);
    __half*   p_hw   = (__half*)symaddr(g_hw);

    // ---- one-time converts ----
    cvt(x, p_hx, N_NODES * DIN_);
    cvt(gat1_W, p_hw + OG1, 256 * 128);
    cvt(gat2_W, p_hw + OG2, 256 * 256);
    cvt(Wqkv,   p_hw + OQKV, 2 * 768 * 256);
    cvt(Wo,     p_hw + OWO,  2 * 256 * 256);
    cvt(Wff1,   p_hw + OFF1, 2 * 1024 * 256);
    cvt(Wff2,   p_hw + OFF2, 2 * 256 * 1024);

    const int TB = 256;
    const int nwb_nodes = (N_NODES * 32 + TB - 1) / TB;
    const int blk_nd    = (N_NODES * DIM + TB - 1) / TB;
    const int blk_e     = (N_E2 + TB - 1) / TB;
    const int nwb_edges = ((size_t)N_E2 * 32 + TB - 1) / TB;

    // ---- GAT layer 1 ----
    launch_gemm<false, false, false>(p_hx, p_hw + OG1, nullptr, p_h, N_NODES, DIM, DIN_);
    gat_scores<<<nwb_nodes, TB>>>(p_h, gat1_asrc, gat1_adst, p_ssrc, p_sdst);
    gat_init<<<blk_nd, TB>>>(p_x1);
    gat_edge_max<<<blk_e, TB>>>(ei, p_ssrc, p_sdst, p_eex, p_nmax);
    gat_edge_exp<<<blk_e, TB>>>(ei, p_eex, p_nmax, p_den);
    gat_scatter<<<nwb_edges, TB>>>(ei, p_eex, p_den, p_h, p_x1);
    bias_relu<true><<<blk_nd, TB>>>(p_x1, gat1_b, p_hx1, N_NODES * DIM);

    // ---- GAT layer 2 ----
    launch_gemm<false, false, false>(p_hx1, p_hw + OG2, nullptr, p_h, N_NODES, DIM, DIM);
    gat_scores<<<nwb_nodes, TB>>>(p_h, gat2_asrc, gat2_adst, p_ssrc, p_sdst);
    gat_init<<<blk_nd, TB>>>(p_x2);
    gat_edge_max<<<blk_e, TB>>>(ei, p_ssrc, p_sdst, p_eex, p_nmax);
    gat_edge_exp<<<blk_e, TB>>>(ei, p_eex, p_nmax, p_den);
    gat_scatter<<<nwb_edges, TB>>>(ei, p_eex, p_den, p_h, p_x2);
    bias_relu<false><<<blk_nd, TB>>>(p_x2, gat2_b, nullptr, N_NODES * DIM);

    // ---- sequence ----
    build_seq<<<blk_nd, TB>>>(p_x1, p_x2, cls, pos, p_seq, p_hseq);

    // ---- transformer ----
    const int nwb_attn = (N_NODES * 4 * 32 + TB - 1) / TB;
    const int blk_ln   = (SEQROWS + 7) / 8;

    for (int l = 0; l < 2; l++) {
        const __half* Wq   = p_hw + OQKV + (size_t)l * 768 * 256;
        const float*  bq   = bqkv + (size_t)l * 768;
        const __half* Wo_l = p_hw + OWO + (size_t)l * 256 * 256;
        const float*  bo_l = bo + (size_t)l * 256;
        const __half* W1   = p_hw + OFF1 + (size_t)l * 1024 * 256;
        const float*  b1   = bff1 + (size_t)l * 1024;
        const __half* W2   = p_hw + OFF2 + (size_t)l * 256 * 1024;
        const float*  b2   = bff2 + (size_t)l * 256;

        launch_gemm<true, true, false>(p_hseq, Wq, bq, p_hqkv, SEQROWS, 768, 256);
        mha_attn<<<nwb_attn, TB>>>(p_hqkv, p_hattn);
        launch_gemm<true, true, false>(p_hattn, Wo_l, bo_l, p_hdel, SEQROWS, 256, 256);
        ln_res<<<blk_ln, TB>>>(p_seq, p_hdel, ln1_g + l * 256, ln1_b + l * 256, p_hseq, SEQROWS);
        launch_gemm<true, true, true>(p_hseq, W1, b1, p_hff, SEQROWS, 1024, 256);
        launch_gemm<true, true, false>(p_hff, W2, b2, p_hdel, SEQROWS, 256, 1024);
        ln_res<<<blk_ln, TB>>>(p_seq, p_hdel, ln2_g + l * 256, ln2_b + l * 256, p_hseq, SEQROWS);
    }

    ln_out<<<(N_NODES + 7) / 8, TB>>>(p_seq, norm_g, norm_b, out);
}

// round 12
// speedup vs baseline: 1.4499x; 1.4293x over previous
#include <cuda_runtime.h>
#include <cuda_fp16.h>
#include <cstdint>

#define N_NODES 50000
#define N_EDGES 320000
#define N_E2    370000
#define DIM     256
#define DIN_    128
#define SEQROWS (3*N_NODES)

// ---------------- fp32 scratch ----------------
__device__ float    g_h   [N_NODES*DIM];
__device__ float    g_x1  [N_NODES*DIM];
__device__ float    g_x2  [N_NODES*DIM];
__device__ float    g_ssrc[N_NODES];
__device__ float    g_sdst[N_NODES];
__device__ unsigned g_nmax[N_NODES];
__device__ float    g_den [N_NODES];
__device__ float    g_eex [N_E2];
__device__ float    g_seq [SEQROWS*DIM];
__device__ float    g_big1[(size_t)SEQROWS*256];

// ---------------- fp16 scratch ----------------
__device__ __half g_hx  [N_NODES*DIN_];
__device__ __half g_hx1 [N_NODES*DIM];
__device__ __half g_hseq[SEQROWS*DIM];
__device__ __half g_hattn[SEQROWS*DIM];
__device__ __half g_hqkv[(size_t)SEQROWS*768];
__device__ __half g_hff [(size_t)SEQROWS*1024];
// packed half weights
#define OG1  0
#define OG2  (OG1 + 256*128)
#define OQKV (OG2 + 256*256)
#define OWO  (OQKV + 2*768*256)
#define OFF1 (OWO + 2*256*256)
#define OFF2 (OFF1 + 2*1024*256)
#define HWTOT (OFF2 + 2*256*1024)
__device__ __half g_hw[HWTOT];

__device__ __forceinline__ float warp_sum(float v) {
#pragma unroll
    for (int o = 16; o; o >>= 1) v += __shfl_xor_sync(0xffffffffu, v, o);
    return v;
}
__device__ __forceinline__ void red_add4(float* p, float4 v) {
    asm volatile("red.global.add.v4.f32 [%0], {%1, %2, %3, %4};"
                 :: "l"(p), "f"(v.x), "f"(v.y), "f"(v.z), "f"(v.w) : "memory");
}
__device__ __forceinline__ uint32_t smem_u32(const void* p) {
    uint32_t a;
    asm("{ .reg .u64 t; cvta.to.shared.u64 t, %1; cvt.u32.u64 %0, t; }" : "=r"(a) : "l"(p));
    return a;
}
__device__ __forceinline__ uint32_t packh2(float x, float y) {
    uint32_t r;
    asm("cvt.rn.f16x2.f32 %0, %1, %2;" : "=r"(r) : "f"(y), "f"(x));
    return r;
}

// ---------------- f32 -> f16 convert ----------------
__global__ void cvt_f2h(const float* __restrict__ s, __half* __restrict__ d, int n)
{
    const int i = (blockIdx.x * blockDim.x + threadIdx.x) * 4;
    if (i >= n) return;
    float4 v = *(const float4*)(s + i);
    uint32_t* o = (uint32_t*)(d + i);
    o[0] = packh2(v.x, v.y);
    o[1] = packh2(v.z, v.w);
}

// ============== fp16 cp.async GEMM: C[M,Nn] = A[M,K] @ W[Nn,K]^T ==============
// CTA 128x128, BK=64 (128B rows, XOR swizzle), 256 threads, warp tile 64x32.
#define TILEB 16384
#define BUFB  (2*TILEB)
#define GSMEM (2*BUFB)              // 65536

__device__ __forceinline__ void cp16(uint32_t s, const void* g) {
    asm volatile("cp.async.cg.shared.global [%0], [%1], 16;" :: "r"(s), "l"(g));
}
__device__ __forceinline__ void ldsm4(uint32_t& r0, uint32_t& r1, uint32_t& r2, uint32_t& r3,
                                      uint32_t addr) {
    asm volatile("ldmatrix.sync.aligned.m8n8.x4.shared.b16 {%0,%1,%2,%3}, [%4];"
                 : "=r"(r0), "=r"(r1), "=r"(r2), "=r"(r3) : "r"(addr));
}
__device__ __forceinline__ void mma_f16(float* c, uint32_t a0, uint32_t a1,
                                        uint32_t a2, uint32_t a3,
                                        uint32_t b0, uint32_t b1) {
    asm volatile(
        "mma.sync.aligned.m16n8k16.row.col.f32.f16.f16.f32 "
        "{%0,%1,%2,%3}, {%4,%5,%6,%7}, {%8,%9}, {%0,%1,%2,%3};"
        : "+f"(c[0]), "+f"(c[1]), "+f"(c[2]), "+f"(c[3])
        : "r"(a0), "r"(a1), "r"(a2), "r"(a3), "r"(b0), "r"(b1));
}

template<bool OUT_HALF, bool BIAS, bool RELU>
__global__ void __launch_bounds__(256, 2) hgemm(
    const __half* __restrict__ A, const __half* __restrict__ W,
    const float* __restrict__ bias, void* __restrict__ Cv,
    int M, int Nn, int K)
{
    extern __shared__ char smraw[];
    const int tid  = threadIdx.x;
    const int lane = tid & 31;
    const int wid  = tid >> 5;
    const int warp_m = wid >> 2;
    const int warp_n = wid & 3;
    const int g  = lane >> 2;
    const int cl = lane & 3;
    const int bm0 = blockIdx.x * 128;
    const int bn0 = blockIdx.y * 128;
    const uint32_t smem_byte = smem_u32(smraw);

    float acc[4][4][4];
#pragma unroll
    for (int mi = 0; mi < 4; mi++)
#pragma unroll
        for (int ni = 0; ni < 4; ni++)
#pragma unroll
            for (int c = 0; c < 4; c++) acc[mi][ni][c] = 0.f;

    const int stages = K >> 6;
    const int ld_r = tid >> 3;
    const int ld_c = tid & 7;

    auto issue = [&](int s) {
        const uint32_t abase = smem_byte + (uint32_t)(s & 1) * BUFB;
        const uint32_t bbase = abase + TILEB;
        const int k0 = s << 6;
#pragma unroll
        for (int i = 0; i < 4; i++) {
            const int r = ld_r + 32 * i;
            const uint32_t sw = (uint32_t)((ld_c ^ (r & 7)) << 4);
            int ar = bm0 + r; if (ar > M - 1) ar = M - 1;
            cp16(abase + (uint32_t)r * 128 + sw, A + (size_t)ar * K + k0 + ld_c * 8);
            cp16(bbase + (uint32_t)r * 128 + sw, W + (size_t)(bn0 + r) * K + k0 + ld_c * 8);
        }
        asm volatile("cp.async.commit_group;" ::: "memory");
    };

    issue(0);
    for (int s = 0; s < stages; s++) {
        if (s + 1 < stages) {
            issue(s + 1);
            asm volatile("cp.async.wait_group 1;" ::: "memory");
        } else {
            asm volatile("cp.async.wait_group 0;" ::: "memory");
        }
        __syncthreads();

        const uint32_t Ab = smem_byte + (uint32_t)(s & 1) * BUFB;
        const uint32_t Bb = Ab + TILEB;
        const int row_a = warp_m * 64 + (lane & 15);
        const int ca = lane >> 4;
        const int row_b0 = warp_n * 32 + (lane & 7) + ((lane >> 4) & 1) * 8;
        const int cb = (lane >> 3) & 1;

#pragma unroll
        for (int kq = 0; kq < 4; kq++) {
            const int kb = kq * 2;
            uint32_t afr[4][4];
            uint32_t bfr[4][2];
            const uint32_t sw_a = (uint32_t)(((kb + ca) ^ (lane & 7)) << 4);
#pragma unroll
            for (int mi = 0; mi < 4; mi++)
                ldsm4(afr[mi][0], afr[mi][1], afr[mi][2], afr[mi][3],
                      Ab + (uint32_t)(row_a + mi * 16) * 128 + sw_a);
            const uint32_t sw_b = (uint32_t)(((kb + cb) ^ (lane & 7)) << 4);
#pragma unroll
            for (int p = 0; p < 2; p++)
                ldsm4(bfr[2*p][0], bfr[2*p][1], bfr[2*p+1][0], bfr[2*p+1][1],
                      Bb + (uint32_t)(row_b0 + p * 16) * 128 + sw_b);
#pragma unroll
            for (int mi = 0; mi < 4; mi++)
#pragma unroll
                for (int ni = 0; ni < 4; ni++)
                    mma_f16(acc[mi][ni], afr[mi][0], afr[mi][1], afr[mi][2], afr[mi][3],
                            bfr[ni][0], bfr[ni][1]);
        }
        __syncthreads();
    }

    // epilogue
#pragma unroll
    for (int mi = 0; mi < 4; mi++) {
        const int r0 = bm0 + warp_m * 64 + mi * 16 + g;
#pragma unroll
        for (int ni = 0; ni < 4; ni++) {
            const int col = bn0 + warp_n * 32 + ni * 8 + 2 * cl;
            float bx = 0.f, by = 0.f;
            if (BIAS) { bx = __ldg(bias + col); by = __ldg(bias + col + 1); }
            float2 v0, v1;
            v0.x = acc[mi][ni][0] + bx; v0.y = acc[mi][ni][1] + by;
            v1.x = acc[mi][ni][2] + bx; v1.y = acc[mi][ni][3] + by;
            if (RELU) {
                v0.x = fmaxf(v0.x, 0.f); v0.y = fmaxf(v0.y, 0.f);
                v1.x = fmaxf(v1.x, 0.f); v1.y = fmaxf(v1.y, 0.f);
            }
            if (OUT_HALF) {
                __half* Ch = (__half*)Cv;
                if (r0 < M)     *(uint32_t*)(Ch + (size_t)r0 * Nn + col)       = packh2(v0.x, v0.y);
                if (r0 + 8 < M) *(uint32_t*)(Ch + (size_t)(r0 + 8) * Nn + col) = packh2(v1.x, v1.y);
            } else {
                float* C = (float*)Cv;
                if (r0 < M)     *(float2*)(C + (size_t)r0 * Nn + col)       = v0;
                if (r0 + 8 < M) *(float2*)(C + (size_t)(r0 + 8) * Nn + col) = v1;
            }
        }
    }
}

// ---------------- GAT ----------------
__global__ void gat_scores(const float* __restrict__ h,
                           const float* __restrict__ asrc, const float* __restrict__ adst,
                           float* __restrict__ ssrc, float* __restrict__ sdst)
{
    const int gw = (int)(((size_t)blockIdx.x * blockDim.x + threadIdx.x) >> 5);
    const int lane = threadIdx.x & 31;
    if (gw >= N_NODES) return;
    const float4* hp = (const float4*)(h + (size_t)gw * DIM);
    float s1 = 0.f, s2 = 0.f;
#pragma unroll
    for (int i = 0; i < 2; i++) {
        float4 hv = hp[lane + 32 * i];
        float4 a1 = ((const float4*)asrc)[lane + 32 * i];
        float4 a2 = ((const float4*)adst)[lane + 32 * i];
        s1 += hv.x*a1.x + hv.y*a1.y + hv.z*a1.z + hv.w*a1.w;
        s2 += hv.x*a2.x + hv.y*a2.y + hv.z*a2.z + hv.w*a2.w;
    }
    s1 = warp_sum(s1); s2 = warp_sum(s2);
    if (lane == 0) { ssrc[gw] = s1; sdst[gw] = s2; }
}

__global__ void gat_init(float* __restrict__ acc)
{
    const int idx = blockIdx.x * blockDim.x + threadIdx.x;
    if (idx < N_NODES * DIM) acc[idx] = 0.f;
    if (idx < N_NODES) { g_den[idx] = 0.f; g_nmax[idx] = 0u; }
}

__device__ __forceinline__ unsigned ord_enc(float f) {
    unsigned u = __float_as_uint(f);
    return (u & 0x80000000u) ? ~u : (u | 0x80000000u);
}
__device__ __forceinline__ float ord_dec(unsigned u) {
    return __uint_as_float((u & 0x80000000u) ? (u ^ 0x80000000u) : ~u);
}

__global__ void gat_edge_max(const int* __restrict__ ei,
                             const float* __restrict__ ssrc, const float* __restrict__ sdst,
                             float* __restrict__ e_out, unsigned* __restrict__ nmax)
{
    const int k = blockIdx.x * blockDim.x + threadIdx.x;
    if (k >= N_E2) return;
    const int s = (k < N_EDGES) ? ei[k] : (k - N_EDGES);
    const int d = (k < N_EDGES) ? ei[N_EDGES + k] : (k - N_EDGES);
    float e = ssrc[s] + sdst[d];
    e = (e >= 0.f) ? e : 0.2f * e;
    e_out[k] = e;
    atomicMax(&nmax[d], ord_enc(e));
}

__global__ void gat_edge_exp(const int* __restrict__ ei,
                             float* __restrict__ e_inout,
                             const unsigned* __restrict__ nmax, float* __restrict__ den)
{
    const int k = blockIdx.x * blockDim.x + threadIdx.x;
    if (k >= N_E2) return;
    const int d = (k < N_EDGES) ? ei[N_EDGES + k] : (k - N_EDGES);
    const float m = ord_dec(nmax[d]);
    const float ex = expf(e_inout[k] - m);
    e_inout[k] = ex;
    atomicAdd(&den[d], ex);
}

__global__ void gat_scatter(const int* __restrict__ ei,
                            const float* __restrict__ ex, const float* __restrict__ den,
                            const float* __restrict__ h, float* __restrict__ out)
{
    const int gw = (int)(((size_t)blockIdx.x * blockDim.x + threadIdx.x) >> 5);
    const int lane = threadIdx.x & 31;
    if (gw >= N_E2) return;
    const int s = (gw < N_EDGES) ? ei[gw] : (gw - N_EDGES);
    const int d = (gw < N_EDGES) ? ei[N_EDGES + gw] : (gw - N_EDGES);
    const float alpha = ex[gw] / den[d];
    const float4* hp = (const float4*)(h + (size_t)s * DIM);
    float* op = out + (size_t)d * DIM;
#pragma unroll
    for (int i = 0; i < 2; i++) {
        float4 v = hp[lane + 32 * i];
        v.x *= alpha; v.y *= alpha; v.z *= alpha; v.w *= alpha;
        red_add4(op + (size_t)(lane + 32 * i) * 4, v);
    }
}

template<bool WRITE_H>
__global__ void bias_relu(float* __restrict__ x, const float* __restrict__ b,
                          __half* __restrict__ xh, int total)
{
    const int idx = blockIdx.x * blockDim.x + threadIdx.x;
    if (idx >= total) return;
    const float v = fmaxf(x[idx] + b[idx & (DIM - 1)], 0.f);
    x[idx] = v;
    if (WRITE_H) xh[idx] = __float2half(v);
}

// fused: x2 = relu(x2_acc + b); seq/hseq build for all 3 tokens
__global__ void gat2_finish(const float* __restrict__ x2acc, const float* __restrict__ b,
                            const float* __restrict__ x1,
                            const float* __restrict__ cls, const float* __restrict__ pos,
                            float* __restrict__ seq, __half* __restrict__ seqh)
{
    const int idx = blockIdx.x * blockDim.x + threadIdx.x;
    if (idx >= N_NODES * DIM) return;
    const int d = idx & (DIM - 1);
    const size_t bq = (size_t)(idx >> 8) * 3 * DIM;
    const float v2r = fmaxf(x2acc[idx] + b[d], 0.f);
    const float v0 = cls[d]  + pos[d];
    const float v1 = x1[idx] + pos[DIM + d];
    const float v2 = v2r     + pos[2 * DIM + d];
    seq[bq + d] = v0;           seqh[bq + d] = __float2half(v0);
    seq[bq + DIM + d] = v1;     seqh[bq + DIM + d] = __float2half(v1);
    seq[bq + 2*DIM + d] = v2;   seqh[bq + 2*DIM + d] = __float2half(v2);
}

__global__ void mha_attn(const __half* __restrict__ qkv, __half* __restrict__ o)
{
    const int gw = (int)(((size_t)blockIdx.x * blockDim.x + threadIdx.x) >> 5);
    const int lane = threadIdx.x & 31;
    if (gw >= N_NODES * 4) return;
    const int n = gw >> 2, h = gw & 3;
    const __half* base = qkv + (size_t)n * (3 * 768) + h * 64;
    float q[3][2], k[3][2], v[3][2];
#pragma unroll
    for (int i = 0; i < 3; i++) {
        q[i][0] = __half2float(base[i*768 + lane]);
        q[i][1] = __half2float(base[i*768 + lane + 32]);
        k[i][0] = __half2float(base[i*768 + 256 + lane]);
        k[i][1] = __half2float(base[i*768 + 256 + lane + 32]);
        v[i][0] = __half2float(base[i*768 + 512 + lane]);
        v[i][1] = __half2float(base[i*768 + 512 + lane + 32]);
    }
    float lg[3][3];
#pragma unroll
    for (int i = 0; i < 3; i++)
#pragma unroll
        for (int j = 0; j < 3; j++)
            lg[i][j] = warp_sum(q[i][0]*k[j][0] + q[i][1]*k[j][1]) * 0.125f;
#pragma unroll
    for (int i = 0; i < 3; i++) {
        const float m = fmaxf(lg[i][0], fmaxf(lg[i][1], lg[i][2]));
        const float e0 = expf(lg[i][0] - m), e1 = expf(lg[i][1] - m), e2 = expf(lg[i][2] - m);
        const float inv = 1.f / (e0 + e1 + e2);
        const float a0 = e0 * inv, a1 = e1 * inv, a2 = e2 * inv;
        const float o0 = a0*v[0][0] + a1*v[1][0] + a2*v[2][0];
        const float o1 = a0*v[0][1] + a1*v[1][1] + a2*v[2][1];
        const size_t ob = (size_t)n * 768 + i * 256 + h * 64;
        o[ob + lane]      = __float2half(o0);
        o[ob + lane + 32] = __float2half(o1);
    }
}

__global__ void ln_res(float* __restrict__ x, const float* __restrict__ delta,
                       const float* __restrict__ g, const float* __restrict__ b,
                       __half* __restrict__ xh, int rows)
{
    const int row = blockIdx.x * 8 + (threadIdx.x >> 5);
    const int lane = threadIdx.x & 31;
    if (row >= rows) return;
    float4* xp = (float4*)(x + (size_t)row * DIM);
    const float4* dp = (const float4*)(delta + (size_t)row * DIM);
    float4 v0 = xp[lane], v1 = xp[lane + 32];
    float4 d0 = dp[lane], d1 = dp[lane + 32];
    v0.x += d0.x; v0.y += d0.y; v0.z += d0.z; v0.w += d0.w;
    v1.x += d1.x; v1.y += d1.y; v1.z += d1.z; v1.w += d1.w;
    float s  = v0.x + v0.y + v0.z + v0.w + v1.x + v1.y + v1.z + v1.w;
    float s2 = v0.x*v0.x + v0.y*v0.y + v0.z*v0.z + v0.w*v0.w
             + v1.x*v1.x + v1.y*v1.y + v1.z*v1.z + v1.w*v1.w;
    s = warp_sum(s); s2 = warp_sum(s2);
    const float mean = s * (1.f / DIM);
    const float var  = s2 * (1.f / DIM) - mean * mean;
    const float inv = rsqrtf(var + 1e-5f);
    float4 g0 = ((const float4*)g)[lane], g1 = ((const float4*)g)[lane + 32];
    float4 b0 = ((const float4*)b)[lane], b1 = ((const float4*)b)[lane + 32];
    v0.x = (v0.x - mean) * inv * g0.x + b0.x; v0.y = (v0.y - mean) * inv * g0.y + b0.y;
    v0.z = (v0.z - mean) * inv * g0.z + b0.z; v0.w = (v0.w - mean) * inv * g0.w + b0.w;
    v1.x = (v1.x - mean) * inv * g1.x + b1.x; v1.y = (v1.y - mean) * inv * g1.y + b1.y;
    v1.z = (v1.z - mean) * inv * g1.z + b1.z; v1.w = (v1.w - mean) * inv * g1.w + b1.w;
    xp[lane] = v0; xp[lane + 32] = v1;
    uint2* hp = (uint2*)(xh + (size_t)row * DIM);
    uint2 h0, h1;
    h0.x = packh2(v0.x, v0.y); h0.y = packh2(v0.z, v0.w);
    h1.x = packh2(v1.x, v1.y); h1.y = packh2(v1.z, v1.w);
    hp[lane] = h0; hp[lane + 32] = h1;
}

__global__ void ln_out(const float* __restrict__ seq,
                       const float* __restrict__ g, const float* __restrict__ b,
                       float* __restrict__ out)
{
    const int row = blockIdx.x * 8 + (threadIdx.x >> 5);
    const int lane = threadIdx.x & 31;
    if (row >= N_NODES) return;
    const float4* xp = (const float4*)(seq + (size_t)row * 768);
    float4 v0 = xp[lane], v1 = xp[lane + 32];
    float s  = v0.x + v0.y + v0.z + v0.w + v1.x + v1.y + v1.z + v1.w;
    float s2 = v0.x*v0.x + v0.y*v0.y + v0.z*v0.z + v0.w*v0.w
             + v1.x*v1.x + v1.y*v1.y + v1.z*v1.z + v1.w*v1.w;
    s = warp_sum(s); s2 = warp_sum(s2);
    const float mean = s * (1.f / DIM);
    const float var  = s2 * (1.f / DIM) - mean * mean;
    const float inv = rsqrtf(var + 1e-5f);
    float4 g0 = ((const float4*)g)[lane], g1 = ((const float4*)g)[lane + 32];
    float4 b0 = ((const float4*)b)[lane], b1 = ((const float4*)b)[lane + 32];
    v0.x = (v0.x - mean) * inv * g0.x + b0.x; v0.y = (v0.y - mean) * inv * g0.y + b0.y;
    v0.z = (v0.z - mean) * inv * g0.z + b0.z; v0.w = (v0.w - mean) * inv * g0.w + b0.w;
    v1.x = (v1.x - mean) * inv * g1.x + b1.x; v1.y = (v1.y - mean) * inv * g1.y + b1.y;
    v1.z = (v1.z - mean) * inv * g1.z + b1.z; v1.w = (v1.w - mean) * inv * g1.w + b1.w;
    float4* op = (float4*)(out + (size_t)row * DIM);
    op[lane] = v0; op[lane + 32] = v1;
}

// ---------------- host ----------------
static void* symaddr(const void* sym) {
    void* p = nullptr;
    cudaGetSymbolAddress(&p, sym);
    return p;
}

template<bool OUT_HALF, bool BIAS, bool RELU>
static void launch_gemm(const __half* A, const __half* W, const float* bias, void* C,
                        int M, int Nn, int K)
{
    cudaFuncSetAttribute(hgemm<OUT_HALF, BIAS, RELU>,
                         cudaFuncAttributeMaxDynamicSharedMemorySize, GSMEM);
    dim3 grid((M + 127) / 128, Nn / 128);
    hgemm<OUT_HALF, BIAS, RELU><<<grid, 256, GSMEM>>>(A, W, bias, C, M, Nn, K);
}

static void cvt(const float* s, __half* d, int n) {
    cvt_f2h<<<(n / 4 + 255) / 256, 256>>>(s, d, n);
}

extern "C" void kernel_launch(void* const* d_in, const int* in_sizes, int n_in,
                              void* d_out, int out_size)
{
    (void)in_sizes; (void)n_in; (void)out_size;
    const float* x         = (const float*)d_in[0];
    const int*   ei        = (const int*)  d_in[1];
    const float* gat1_W    = (const float*)d_in[2];
    const float* gat1_b    = (const float*)d_in[3];
    const float* gat1_asrc = (const float*)d_in[4];
    const float* gat1_adst = (const float*)d_in[5];
    const float* gat2_W    = (const float*)d_in[6];
    const float* gat2_b    = (const float*)d_in[7];
    const float* gat2_asrc = (const float*)d_in[8];
    const float* gat2_adst = (const float*)d_in[9];
    const float* cls       = (const float*)d_in[10];
    const float* pos       = (const float*)d_in[11];
    const float* Wqkv      = (const float*)d_in[12];
    const float* bqkv      = (const float*)d_in[13];
    const float* Wo        = (const float*)d_in[14];
    const float* bo        = (const float*)d_in[15];
    const float* ln1_g     = (const float*)d_in[16];
    const float* ln1_b     = (const float*)d_in[17];
    const float* ln2_g     = (const float*)d_in[18];
    const float* ln2_b     = (const float*)d_in[19];
    const float* Wff1      = (const float*)d_in[20];
    const float* bff1      = (const float*)d_in[21];
    const float* Wff2      = (const float*)d_in[22];
    const float* bff2      = (const float*)d_in[23];
    const float* norm_g    = (const float*)d_in[24];
    const float* norm_b    = (const float*)d_in[25];
    float* out = (float*)d_out;

    float*    p_h    = (float*)symaddr(g_h);
    float*    p_x1   = (float*)symaddr(g_x1);
    float*    p_x2   = (float*)symaddr(g_x2);
    float*    p_ssrc = (float*)symaddr(g_ssrc);
    float*    p_sdst = (float*)symaddr(g_sdst);
    unsigned* p_nmax = (unsigned*)symaddr(g_nmax);
    float*    p_den  = (float*)symaddr(g_den);
    float*    p_eex  = (float*)symaddr(g_eex);
    float*    p_seq  = (float*)symaddr(g_seq);
    float*    p_big1 = (float*)symaddr(g_big1);
    __half*   p_hx   = (__half*)symaddr(g_hx);
    __half*   p_hx1  = (__half*)symaddr(g_hx1);
    __half*   p_hseq = (__half*)symaddr(g_hseq);
    __half*   p_hattn= (__half*)symaddr(g_hattn);
    __half*   p_hqkv = (__half*)symaddr(g_hqkv);
    __half*   p_hff  = (__half*)symaddr(g_hff);
    __half*   p_hw   = (__half*)symaddr(g_hw);

    // ---- one-time converts ----
    cvt(x, p_hx, N_NODES * DIN_);
    cvt(gat1_W, p_hw + OG1, 256 * 128);
    cvt(gat2_W, p_hw + OG2, 256 * 256);
    cvt(Wqkv,   p_hw + OQKV, 2 * 768 * 256);
    cvt(Wo,     p_hw + OWO,  2 * 256 * 256);
    cvt(Wff1,   p_hw + OFF1, 2 * 1024 * 256);
    cvt(Wff2,   p_hw + OFF2, 2 * 256 * 1024);

    const int TB = 256;
    const int nwb_nodes = (N_NODES * 32 + TB - 1) / TB;
    const int blk_nd    = (N_NODES * DIM + TB - 1) / TB;
    const int blk_e     = (N_E2 + TB - 1) / TB;
    const int nwb_edges = ((size_t)N_E2 * 32 + TB - 1) / TB;

    // ---- GAT layer 1 ----
    launch_gemm<false, false, false>(p_hx, p_hw + OG1, nullptr, p_h, N_NODES, DIM, DIN_);
    gat_scores<<<nwb_nodes, TB>>>(p_h, gat1_asrc, gat1_adst, p_ssrc, p_sdst);
    gat_init<<<blk_nd, TB>>>(p_x1);
    gat_edge_max<<<blk_e, TB>>>(ei, p_ssrc, p_sdst, p_eex, p_nmax);
    gat_edge_exp<<<blk_e, TB>>>(ei, p_eex, p_nmax, p_den);
    gat_scatter<<<nwb_edges, TB>>>(ei, p_eex, p_den, p_h, p_x1);
    bias_relu<true><<<blk_nd, TB>>>(p_x1, gat1_b, p_hx1, N_NODES * DIM);

    // ---- GAT layer 2 ----
    launch_gemm<false, false, false>(p_hx1, p_hw + OG2, nullptr, p_h, N_NODES, DIM, DIM);
    gat_scores<<<nwb_nodes, TB>>>(p_h, gat2_asrc, gat2_adst, p_ssrc, p_sdst);
    gat_init<<<blk_nd, TB>>>(p_x2);
    gat_edge_max<<<blk_e, TB>>>(ei, p_ssrc, p_sdst, p_eex, p_nmax);
    gat_edge_exp<<<blk_e, TB>>>(ei, p_eex, p_nmax, p_den);
    gat_scatter<<<nwb_edges, TB>>>(ei, p_eex, p_den, p_h, p_x2);

    // ---- fused bias+relu(x2) + sequence build ----
    gat2_finish<<<blk_nd, TB>>>(p_x2, gat2_b, p_x1, cls, pos, p_seq, p_hseq);

    // ---- transformer ----
    const int nwb_attn = (N_NODES * 4 * 32 + TB - 1) / TB;
    const int blk_ln   = (SEQROWS + 7) / 8;

    for (int l = 0; l < 2; l++) {
        const __half* Wq   = p_hw + OQKV + (size_t)l * 768 * 256;
        const float*  bq   = bqkv + (size_t)l * 768;
        const __half* Wo_l = p_hw + OWO + (size_t)l * 256 * 256;
        const float*  bo_l = bo + (size_t)l * 256;
        const __half* W1   = p_hw + OFF1 + (size_t)l * 1024 * 256;
        const float*  b1   = bff1 + (size_t)l * 1024;
        const __half* W2   = p_hw + OFF2 + (size_t)l * 256 * 1024;
        const float*  b2   = bff2 + (size_t)l * 256;

        launch_gemm<true, true, false>(p_hseq, Wq, bq, p_hqkv, SEQROWS, 768, 256);
        mha_attn<<<nwb_attn, TB>>>(p_hqkv, p_hattn);
        launch_gemm<false, true, false>(p_hattn, Wo_l, bo_l, p_big1, SEQROWS, 256, 256);
        ln_res<<<blk_ln, TB>>>(p_seq, p_big1, ln1_g + l * 256, ln1_b + l * 256, p_hseq, SEQROWS);
        launch_gemm<true, true, true>(p_hseq, W1, b1, p_hff, SEQROWS, 1024, 256);
        launch_gemm<false, true, false>(p_hff, W2, b2, p_big1, SEQROWS, 256, 1024);
        ln_res<<<blk_ln, TB>>>(p_seq, p_big1, ln2_g + l * 256, ln2_b + l * 256, p_hseq, SEQROWS);
    }

    ln_out<<<(N_NODES + 7) / 8, TB>>>(p_seq, norm_g, norm_b, out);
}

// round 14
// speedup vs baseline: 1.4858x; 1.0248x over previous
#include <cuda_runtime.h>
#include <cuda_fp16.h>
#include <cstdint>

#define N_NODES 50000
#define N_EDGES 320000
#define N_E2    370000
#define DIM     256
#define DIN_    128
#define SEQROWS (3*N_NODES)

// ---------------- fp32 scratch ----------------
__device__ float    g_h   [N_NODES*DIM];
__device__ float    g_x1  [N_NODES*DIM];
__device__ float    g_x2  [N_NODES*DIM];
__device__ float    g_ssrc[N_NODES];
__device__ float    g_sdst[N_NODES];
__device__ unsigned g_nmax[N_NODES];
__device__ float    g_den [N_NODES];
__device__ float    g_eex [N_E2];
__device__ float    g_seq [SEQROWS*DIM];
__device__ float    g_big1[(size_t)SEQROWS*256];

// ---------------- fp16 scratch ----------------
__device__ __half g_hx  [N_NODES*DIN_];
__device__ __half g_hx1 [N_NODES*DIM];
__device__ __half g_hseq[SEQROWS*DIM];
__device__ __half g_hattn[SEQROWS*DIM];
__device__ __half g_hqkv[(size_t)SEQROWS*768];
__device__ __half g_hff [(size_t)SEQROWS*1024];
// packed half weights
#define OG1  0
#define OG2  (OG1 + 256*128)
#define OQKV (OG2 + 256*256)
#define OWO  (OQKV + 2*768*256)
#define OFF1 (OWO + 2*256*256)
#define OFF2 (OFF1 + 2*1024*256)
#define HWTOT (OFF2 + 2*256*1024)
__device__ __half g_hw[HWTOT];

__device__ __forceinline__ float warp_sum(float v) {
#pragma unroll
    for (int o = 16; o; o >>= 1) v += __shfl_xor_sync(0xffffffffu, v, o);
    return v;
}
__device__ __forceinline__ void red_add4(float* p, float4 v) {
    asm volatile("red.global.add.v4.f32 [%0], {%1, %2, %3, %4};"
                 :: "l"(p), "f"(v.x), "f"(v.y), "f"(v.z), "f"(v.w) : "memory");
}
__device__ __forceinline__ uint32_t smem_u32(const void* p) {
    uint32_t a;
    asm("{ .reg .u64 t; cvta.to.shared.u64 t, %1; cvt.u32.u64 %0, t; }" : "=r"(a) : "l"(p));
    return a;
}
__device__ __forceinline__ uint32_t packh2(float x, float y) {
    uint32_t r;
    asm("cvt.rn.f16x2.f32 %0, %1, %2;" : "=r"(r) : "f"(y), "f"(x));
    return r;
}

// ---------------- f32 -> f16 convert ----------------
__global__ void cvt_f2h(const float* __restrict__ s, __half* __restrict__ d, int n)
{
    const int i = (blockIdx.x * blockDim.x + threadIdx.x) * 4;
    if (i >= n) return;
    float4 v = *(const float4*)(s + i);
    uint32_t* o = (uint32_t*)(d + i);
    o[0] = packh2(v.x, v.y);
    o[1] = packh2(v.z, v.w);
}

// ============== fp16 cp.async GEMM: C[M,Nn] = A[M,K] @ W[Nn,K]^T ==============
// CTA 128x128, BK=64 (128B rows, XOR swizzle), 256 threads, warp tile 64x32.
// 3-buffer cp.async pipeline, prefetch depth 2, one barrier per stage.
#define TILEB 16384
#define BUFB  (2*TILEB)
#define GSMEM (3*BUFB)              // 98304

__device__ __forceinline__ void cp16(uint32_t s, const void* g) {
    asm volatile("cp.async.cg.shared.global [%0], [%1], 16;" :: "r"(s), "l"(g));
}
__device__ __forceinline__ void ldsm4(uint32_t& r0, uint32_t& r1, uint32_t& r2, uint32_t& r3,
                                      uint32_t addr) {
    asm volatile("ldmatrix.sync.aligned.m8n8.x4.shared.b16 {%0,%1,%2,%3}, [%4];"
                 : "=r"(r0), "=r"(r1), "=r"(r2), "=r"(r3) : "r"(addr));
}
__device__ __forceinline__ void mma_f16(float* c, uint32_t a0, uint32_t a1,
                                        uint32_t a2, uint32_t a3,
                                        uint32_t b0, uint32_t b1) {
    asm volatile(
        "mma.sync.aligned.m16n8k16.row.col.f32.f16.f16.f32 "
        "{%0,%1,%2,%3}, {%4,%5,%6,%7}, {%8,%9}, {%0,%1,%2,%3};"
        : "+f"(c[0]), "+f"(c[1]), "+f"(c[2]), "+f"(c[3])
        : "r"(a0), "r"(a1), "r"(a2), "r"(a3), "r"(b0), "r"(b1));
}

template<bool OUT_HALF, bool BIAS, bool RELU>
__global__ void __launch_bounds__(256, 2) hgemm(
    const __half* __restrict__ A, const __half* __restrict__ W,
    const float* __restrict__ bias, void* __restrict__ Cv,
    int M, int Nn, int K)
{
    extern __shared__ char smraw[];
    const int tid  = threadIdx.x;
    const int lane = tid & 31;
    const int wid  = tid >> 5;
    const int warp_m = wid >> 2;
    const int warp_n = wid & 3;
    const int g  = lane >> 2;
    const int cl = lane & 3;
    const int bm0 = blockIdx.x * 128;
    const int bn0 = blockIdx.y * 128;
    const uint32_t smem_byte = smem_u32(smraw);

    float acc[4][4][4];
#pragma unroll
    for (int mi = 0; mi < 4; mi++)
#pragma unroll
        for (int ni = 0; ni < 4; ni++)
#pragma unroll
            for (int c = 0; c < 4; c++) acc[mi][ni][c] = 0.f;

    const int stages = K >> 6;
    const int ld_r = tid >> 3;
    const int ld_c = tid & 7;

    auto issue = [&](int s) {
        const uint32_t abase = smem_byte + (uint32_t)(s % 3) * BUFB;
        const uint32_t bbase = abase + TILEB;
        const int k0 = s << 6;
#pragma unroll
        for (int i = 0; i < 4; i++) {
            const int r = ld_r + 32 * i;
            const uint32_t sw = (uint32_t)((ld_c ^ (r & 7)) << 4);
            int ar = bm0 + r; if (ar > M - 1) ar = M - 1;
            cp16(abase + (uint32_t)r * 128 + sw, A + (size_t)ar * K + k0 + ld_c * 8);
            cp16(bbase + (uint32_t)r * 128 + sw, W + (size_t)(bn0 + r) * K + k0 + ld_c * 8);
        }
        asm volatile("cp.async.commit_group;" ::: "memory");
    };

    issue(0);
    if (stages > 1) issue(1);

    for (int s = 0; s < stages; s++) {
        if (s + 1 < stages) {
            asm volatile("cp.async.wait_group 1;" ::: "memory");
        } else {
            asm volatile("cp.async.wait_group 0;" ::: "memory");
        }
        __syncthreads();
        if (s + 2 < stages) issue(s + 2);

        const uint32_t Ab = smem_byte + (uint32_t)(s % 3) * BUFB;
        const uint32_t Bb = Ab + TILEB;
        const int row_a = warp_m * 64 + (lane & 15);
        const int ca = lane >> 4;
        const int row_b0 = warp_n * 32 + (lane & 7) + ((lane >> 4) & 1) * 8;
        const int cb = (lane >> 3) & 1;

#pragma unroll
        for (int kq = 0; kq < 4; kq++) {
            const int kb = kq * 2;
            uint32_t afr[4][4];
            uint32_t bfr[4][2];
            const uint32_t sw_a = (uint32_t)(((kb + ca) ^ (lane & 7)) << 4);
#pragma unroll
            for (int mi = 0; mi < 4; mi++)
                ldsm4(afr[mi][0], afr[mi][1], afr[mi][2], afr[mi][3],
                      Ab + (uint32_t)(row_a + mi * 16) * 128 + sw_a);
            const uint32_t sw_b = (uint32_t)(((kb + cb) ^ (lane & 7)) << 4);
#pragma unroll
            for (int p = 0; p < 2; p++)
                ldsm4(bfr[2*p][0], bfr[2*p][1], bfr[2*p+1][0], bfr[2*p+1][1],
                      Bb + (uint32_t)(row_b0 + p * 16) * 128 + sw_b);
#pragma unroll
            for (int mi = 0; mi < 4; mi++)
#pragma unroll
                for (int ni = 0; ni < 4; ni++)
                    mma_f16(acc[mi][ni], afr[mi][0], afr[mi][1], afr[mi][2], afr[mi][3],
                            bfr[ni][0], bfr[ni][1]);
        }
    }

    // epilogue
#pragma unroll
    for (int mi = 0; mi < 4; mi++) {
        const int r0 = bm0 + warp_m * 64 + mi * 16 + g;
#pragma unroll
        for (int ni = 0; ni < 4; ni++) {
            const int col = bn0 + warp_n * 32 + ni * 8 + 2 * cl;
            float bx = 0.f, by = 0.f;
            if (BIAS) { bx = __ldg(bias + col); by = __ldg(bias + col + 1); }
            float2 v0, v1;
            v0.x = acc[mi][ni][0] + bx; v0.y = acc[mi][ni][1] + by;
            v1.x = acc[mi][ni][2] + bx; v1.y = acc[mi][ni][3] + by;
            if (RELU) {
                v0.x = fmaxf(v0.x, 0.f); v0.y = fmaxf(v0.y, 0.f);
                v1.x = fmaxf(v1.x, 0.f); v1.y = fmaxf(v1.y, 0.f);
            }
            if (OUT_HALF) {
                __half* Ch = (__half*)Cv;
                if (r0 < M)     *(uint32_t*)(Ch + (size_t)r0 * Nn + col)       = packh2(v0.x, v0.y);
                if (r0 + 8 < M) *(uint32_t*)(Ch + (size_t)(r0 + 8) * Nn + col) = packh2(v1.x, v1.y);
            } else {
                float* C = (float*)Cv;
                if (r0 < M)     *(float2*)(C + (size_t)r0 * Nn + col)       = v0;
                if (r0 + 8 < M) *(float2*)(C + (size_t)(r0 + 8) * Nn + col) = v1;
            }
        }
    }
}

// ---------------- GAT ----------------
__global__ void gat_scores(const float* __restrict__ h,
                           const float* __restrict__ asrc, const float* __restrict__ adst,
                           float* __restrict__ ssrc, float* __restrict__ sdst)
{
    const int gw = (int)(((size_t)blockIdx.x * blockDim.x + threadIdx.x) >> 5);
    const int lane = threadIdx.x & 31;
    if (gw >= N_NODES) return;
    const float4* hp = (const float4*)(h + (size_t)gw * DIM);
    float s1 = 0.f, s2 = 0.f;
#pragma unroll
    for (int i = 0; i < 2; i++) {
        float4 hv = hp[lane + 32 * i];
        float4 a1 = ((const float4*)asrc)[lane + 32 * i];
        float4 a2 = ((const float4*)adst)[lane + 32 * i];
        s1 += hv.x*a1.x + hv.y*a1.y + hv.z*a1.z + hv.w*a1.w;
        s2 += hv.x*a2.x + hv.y*a2.y + hv.z*a2.z + hv.w*a2.w;
    }
    s1 = warp_sum(s1); s2 = warp_sum(s2);
    if (lane == 0) { ssrc[gw] = s1; sdst[gw] = s2; }
}

__global__ void gat_init(float* __restrict__ acc)
{
    const int idx = blockIdx.x * blockDim.x + threadIdx.x;
    if (idx < N_NODES * DIM) acc[idx] = 0.f;
    if (idx < N_NODES) { g_den[idx] = 0.f; g_nmax[idx] = 0u; }
}

__device__ __forceinline__ unsigned ord_enc(float f) {
    unsigned u = __float_as_uint(f);
    return (u & 0x80000000u) ? ~u : (u | 0x80000000u);
}
__device__ __forceinline__ float ord_dec(unsigned u) {
    return __uint_as_float((u & 0x80000000u) ? (u ^ 0x80000000u) : ~u);
}

__global__ void gat_edge_max(const int* __restrict__ ei,
                             const float* __restrict__ ssrc, const float* __restrict__ sdst,
                             float* __restrict__ e_out, unsigned* __restrict__ nmax)
{
    const int k = blockIdx.x * blockDim.x + threadIdx.x;
    if (k >= N_E2) return;
    const int s = (k < N_EDGES) ? ei[k] : (k - N_EDGES);
    const int d = (k < N_EDGES) ? ei[N_EDGES + k] : (k - N_EDGES);
    float e = ssrc[s] + sdst[d];
    e = (e >= 0.f) ? e : 0.2f * e;
    e_out[k] = e;
    atomicMax(&nmax[d], ord_enc(e));
}

__global__ void gat_edge_exp(const int* __restrict__ ei,
                             float* __restrict__ e_inout,
                             const unsigned* __restrict__ nmax, float* __restrict__ den)
{
    const int k = blockIdx.x * blockDim.x + threadIdx.x;
    if (k >= N_E2) return;
    const int d = (k < N_EDGES) ? ei[N_EDGES + k] : (k - N_EDGES);
    const float m = ord_dec(nmax[d]);
    const float ex = expf(e_inout[k] - m);
    e_inout[k] = ex;
    atomicAdd(&den[d], ex);
}

__global__ void gat_scatter(const int* __restrict__ ei,
                            const float* __restrict__ ex, const float* __restrict__ den,
                            const float* __restrict__ h, float* __restrict__ out)
{
    const int gw = (int)(((size_t)blockIdx.x * blockDim.x + threadIdx.x) >> 5);
    const int lane = threadIdx.x & 31;
    if (gw >= N_E2) return;
    const int s = (gw < N_EDGES) ? ei[gw] : (gw - N_EDGES);
    const int d = (gw < N_EDGES) ? ei[N_EDGES + gw] : (gw - N_EDGES);
    const float alpha = ex[gw] / den[d];
    const float4* hp = (const float4*)(h + (size_t)s * DIM);
    float* op = out + (size_t)d * DIM;
#pragma unroll
    for (int i = 0; i < 2; i++) {
        float4 v = hp[lane + 32 * i];
        v.x *= alpha; v.y *= alpha; v.z *= alpha; v.w *= alpha;
        red_add4(op + (size_t)(lane + 32 * i) * 4, v);
    }
}

// GAT1 finish: write half x1 only (fp32 x1 not needed downstream)
__global__ void bias_relu_h(const float* __restrict__ x, const float* __restrict__ b,
                            __half* __restrict__ xh, int total)
{
    const int idx = blockIdx.x * blockDim.x + threadIdx.x;
    if (idx >= total) return;
    xh[idx] = __float2half(fmaxf(x[idx] + b[idx & (DIM - 1)], 0.f));
}

// fused: x2 = relu(x2_acc + b); seq/hseq build for all 3 tokens (x1 read as half)
__global__ void gat2_finish(const float* __restrict__ x2acc, const float* __restrict__ b,
                            const __half* __restrict__ x1h,
                            const float* __restrict__ cls, const float* __restrict__ pos,
                            float* __restrict__ seq, __half* __restrict__ seqh)
{
    const int idx = blockIdx.x * blockDim.x + threadIdx.x;
    if (idx >= N_NODES * DIM) return;
    const int d = idx & (DIM - 1);
    const size_t bq = (size_t)(idx >> 8) * 3 * DIM;
    const float v2r = fmaxf(x2acc[idx] + b[d], 0.f);
    const float v0 = cls[d] + pos[d];
    const float v1 = __half2float(x1h[idx]) + pos[DIM + d];
    const float v2 = v2r + pos[2 * DIM + d];
    seq[bq + d] = v0;           seqh[bq + d] = __float2half(v0);
    seq[bq + DIM + d] = v1;     seqh[bq + DIM + d] = __float2half(v1);
    seq[bq + 2*DIM + d] = v2;   seqh[bq + 2*DIM + d] = __float2half(v2);
}

// attention: warp per (node, head); half2 vectorized
__global__ void mha_attn(const __half* __restrict__ qkv, __half* __restrict__ o)
{
    const int gw = (int)(((size_t)blockIdx.x * blockDim.x + threadIdx.x) >> 5);
    const int lane = threadIdx.x & 31;
    if (gw >= N_NODES * 4) return;
    const int n = gw >> 2, h = gw & 3;
    const __half* base = qkv + (size_t)n * (3 * 768) + h * 64 + 2 * lane;
    float2 q[3], k[3], v[3];
#pragma unroll
    for (int i = 0; i < 3; i++) {
        q[i] = __half22float2(*(const __half2*)(base + i * 768));
        k[i] = __half22float2(*(const __half2*)(base + i * 768 + 256));
        v[i] = __half22float2(*(const __half2*)(base + i * 768 + 512));
    }
    float lg[3][3];
#pragma unroll
    for (int i = 0; i < 3; i++)
#pragma unroll
        for (int j = 0; j < 3; j++)
            lg[i][j] = warp_sum(q[i].x * k[j].x + q[i].y * k[j].y) * 0.125f;
    __half* ob = o + (size_t)n * 768 + h * 64 + 2 * lane;
#pragma unroll
    for (int i = 0; i < 3; i++) {
        const float m = fmaxf(lg[i][0], fmaxf(lg[i][1], lg[i][2]));
        const float e0 = expf(lg[i][0] - m), e1 = expf(lg[i][1] - m), e2 = expf(lg[i][2] - m);
        const float inv = 1.f / (e0 + e1 + e2);
        const float a0 = e0 * inv, a1 = e1 * inv, a2 = e2 * inv;
        const float o0 = a0*v[0].x + a1*v[1].x + a2*v[2].x;
        const float o1 = a0*v[0].y + a1*v[1].y + a2*v[2].y;
        *(uint32_t*)(ob + i * 256) = packh2(o0, o1);
    }
}

__global__ void ln_res(float* __restrict__ x, const float* __restrict__ delta,
                       const float* __restrict__ g, const float* __restrict__ b,
                       __half* __restrict__ xh, int rows)
{
    const int row = blockIdx.x * 8 + (threadIdx.x >> 5);
    const int lane = threadIdx.x & 31;
    if (row >= rows) return;
    float4* xp = (float4*)(x + (size_t)row * DIM);
    const float4* dp = (const float4*)(delta + (size_t)row * DIM);
    float4 v0 = xp[lane], v1 = xp[lane + 32];
    float4 d0 = dp[lane], d1 = dp[lane + 32];
    v0.x += d0.x; v0.y += d0.y; v0.z += d0.z; v0.w += d0.w;
    v1.x += d1.x; v1.y += d1.y; v1.z += d1.z; v1.w += d1.w;
    float s  = v0.x + v0.y + v0.z + v0.w + v1.x + v1.y + v1.z + v1.w;
    float s2 = v0.x*v0.x + v0.y*v0.y + v0.z*v0.z + v0.w*v0.w
             + v1.x*v1.x + v1.y*v1.y + v1.z*v1.z + v1.w*v1.w;
    s = warp_sum(s); s2 = warp_sum(s2);
    const float mean = s * (1.f / DIM);
    const float var  = s2 * (1.f / DIM) - mean * mean;
    const float inv = rsqrtf(var + 1e-5f);
    float4 g0 = ((const float4*)g)[lane], g1 = ((const float4*)g)[lane + 32];
    float4 b0 = ((const float4*)b)[lane], b1 = ((const float4*)b)[lane + 32];
    v0.x = (v0.x - mean) * inv * g0.x + b0.x; v0.y = (v0.y - mean) * inv * g0.y + b0.y;
    v0.z = (v0.z - mean) * inv * g0.z + b0.z; v0.w = (v0.w - mean) * inv * g0.w + b0.w;
    v1.x = (v1.x - mean) * inv * g1.x + b1.x; v1.y = (v1.y - mean) * inv * g1.y + b1.y;
    v1.z = (v1.z - mean) * inv * g1.z + b1.z; v1.w = (v1.w - mean) * inv * g1.w + b1.w;
    xp[lane] = v0; xp[lane + 32] = v1;
    uint2* hp = (uint2*)(xh + (size_t)row * DIM);
    uint2 h0, h1;
    h0.x = packh2(v0.x, v0.y); h0.y = packh2(v0.z, v0.w);
    h1.x = packh2(v1.x, v1.y); h1.y = packh2(v1.z, v1.w);
    hp[lane] = h0; hp[lane + 32] = h1;
}

__global__ void ln_out(const float* __restrict__ seq,
                       const float* __restrict__ g, const float* __restrict__ b,
                       float* __restrict__ out)
{
    const int row = blockIdx.x * 8 + (threadIdx.x >> 5);
    const int lane = threadIdx.x & 31;
    if (row >= N_NODES) return;
    const float4* xp = (const float4*)(seq + (size_t)row * 768);
    float4 v0 = xp[lane], v1 = xp[lane + 32];
    float s  = v0.x + v0.y + v0.z + v0.w + v1.x + v1.y + v1.z + v1.w;
    float s2 = v0.x*v0.x + v0.y*v0.y + v0.z*v0.z + v0.w*v0.w
             + v1.x*v1.x + v1.y*v1.y + v1.z*v1.z + v1.w*v1.w;
    s = warp_sum(s); s2 = warp_sum(s2);
    const float mean = s * (1.f / DIM);
    const float var  = s2 * (1.f / DIM) - mean * mean;
    const float inv = rsqrtf(var + 1e-5f);
    float4 g0 = ((const float4*)g)[lane], g1 = ((const float4*)g)[lane + 32];
    float4 b0 = ((const float4*)b)[lane], b1 = ((const float4*)b)[lane + 32];
    v0.x = (v0.x - mean) * inv * g0.x + b0.x; v0.y = (v0.y - mean) * inv * g0.y + b0.y;
    v0.z = (v0.z - mean) * inv * g0.z + b0.z; v0.w = (v0.w - mean) * inv * g0.w + b0.w;
    v1.x = (v1.x - mean) * inv * g1.x + b1.x; v1.y = (v1.y - mean) * inv * g1.y + b1.y;
    v1.z = (v1.z - mean) * inv * g1.z + b1.z; v1.w = (v1.w - mean) * inv * g1.w + b1.w;
    float4* op = (float4*)(out + (size_t)row * DIM);
    op[lane] = v0; op[lane + 32] = v1;
}

// ---------------- host ----------------
static void* symaddr(const void* sym) {
    void* p = nullptr;
    cudaGetSymbolAddress(&p, sym);
    return p;
}

template<bool OUT_HALF, bool BIAS, bool RELU>
static void launch_gemm(const __half* A, const __half* W, const float* bias, void* C,
                        int M, int Nn, int K)
{
    cudaFuncSetAttribute(hgemm<OUT_HALF, BIAS, RELU>,
                         cudaFuncAttributeMaxDynamicSharedMemorySize, GSMEM);
    dim3 grid((M + 127) / 128, Nn / 128);
    hgemm<OUT_HALF, BIAS, RELU><<<grid, 256, GSMEM>>>(A, W, bias, C, M, Nn, K);
}

static void cvt(const float* s, __half* d, int n) {
    cvt_f2h<<<(n / 4 + 255) / 256, 256>>>(s, d, n);
}

extern "C" void kernel_launch(void* const* d_in, const int* in_sizes, int n_in,
                              void* d_out, int out_size)
{
    (void)in_sizes; (void)n_in; (void)out_size;
    const float* x         = (const float*)d_in[0];
    const int*   ei        = (const int*)  d_in[1];
    const float* gat1_W    = (const float*)d_in[2];
    const float* gat1_b    = (const float*)d_in[3];
    const float* gat1_asrc = (const float*)d_in[4];
    const float* gat1_adst = (const float*)d_in[5];
    const float* gat2_W    = (const float*)d_in[6];
    const float* gat2_b    = (const float*)d_in[7];
    const float* gat2_asrc = (const float*)d_in[8];
    const float* gat2_adst = (const float*)d_in[9];
    const float* cls       = (const float*)d_in[10];
    const float* pos       = (const float*)d_in[11];
    const float* Wqkv      = (const float*)d_in[12];
    const float* bqkv      = (const float*)d_in[13];
    const float* Wo        = (const float*)d_in[14];
    const float* bo        = (const float*)d_in[15];
    const float* ln1_g     = (const float*)d_in[16];
    const float* ln1_b     = (const float*)d_in[17];
    const float* ln2_g     = (const float*)d_in[18];
    const float* ln2_b     = (const float*)d_in[19];
    const float* Wff1      = (const float*)d_in[20];
    const float* bff1      = (const float*)d_in[21];
    const float* Wff2      = (const float*)d_in[22];
    const float* bff2      = (const float*)d_in[23];
    const float* norm_g    = (const float*)d_in[24];
    const float* norm_b    = (const float*)d_in[25];
    float* out = (float*)d_out;

    float*    p_h    = (float*)symaddr(g_h);
    float*    p_x1   = (float*)symaddr(g_x1);
    float*    p_x2   = (float*)symaddr(g_x2);
    float*    p_ssrc = (float*)symaddr(g_ssrc);
    float*    p_sdst = (float*)symaddr(g_sdst);
    unsigned* p_nmax = (unsigned*)symaddr(g_nmax);
    float*    p_den  = (float*)symaddr(g_den);
    float*    p_eex  = (float*)symaddr(g_eex);
    float*    p_seq  = (float*)symaddr(g_seq);
    float*    p_big1 = (float*)symaddr(g_big1);
    __half*   p_hx   = (__half*)symaddr(g_hx);
    __half*   p_hx1  = (__half*)symaddr(g_hx1);
    __half*   p_hseq = (__half*)symaddr(g_hseq);
    __half*   p_hattn= (__half*)symaddr(g_hattn);
    __half*   p_hqkv = (__half*)symaddr(g_hqkv);
    __half*   p_hff  = (__half*)symaddr(g_hff);
    __half*   p_hw   = (__half*)symaddr(g_hw);

    // ---- one-time converts ----
    cvt(x, p_hx, N_NODES * DIN_);
    cvt(gat1_W, p_hw + OG1, 256 * 128);
    cvt(gat2_W, p_hw + OG2, 256 * 256);
    cvt(Wqkv,   p_hw + OQKV, 2 * 768 * 256);
    cvt(Wo,     p_hw + OWO,  2 * 256 * 256);
    cvt(Wff1,   p_hw + OFF1, 2 * 1024 * 256);
    cvt(Wff2,   p_hw + OFF2, 2 * 256 * 1024);

    const int TB = 256;
    const int nwb_nodes = (N_NODES * 32 + TB - 1) / TB;
    const int blk_nd    = (N_NODES * DIM + TB - 1) / TB;
    const int blk_e     = (N_E2 + TB - 1) / TB;
    const int nwb_edges = ((size_t)N_E2 * 32 + TB - 1) / TB;

    // ---- GAT layer 1 ----
    launch_gemm<false, false, false>(p_hx, p_hw + OG1, nullptr, p_h, N_NODES, DIM, DIN_);
    gat_scores<<<nwb_nodes, TB>>>(p_h, gat1_asrc, gat1_adst, p_ssrc, p_sdst);
    gat_init<<<blk_nd, TB>>>(p_x1);
    gat_edge_max<<<blk_e, TB>>>(ei, p_ssrc, p_sdst, p_eex, p_nmax);
    gat_edge_exp<<<blk_e, TB>>>(ei, p_eex, p_nmax, p_den);
    gat_scatter<<<nwb_edges, TB>>>(ei, p_eex, p_den, p_h, p_x1);
    bias_relu_h<<<blk_nd, TB>>>(p_x1, gat1_b, p_hx1, N_NODES * DIM);

    // ---- GAT layer 2 ----
    launch_gemm<false, false, false>(p_hx1, p_hw + OG2, nullptr, p_h, N_NODES, DIM, DIM);
    gat_scores<<<nwb_nodes, TB>>>(p_h, gat2_asrc, gat2_adst, p_ssrc, p_sdst);
    gat_init<<<blk_nd, TB>>>(p_x2);
    gat_edge_max<<<blk_e, TB>>>(ei, p_ssrc, p_sdst, p_eex, p_nmax);
    gat_edge_exp<<<blk_e, TB>>>(ei, p_eex, p_nmax, p_den);
    gat_scatter<<<nwb_edges, TB>>>(ei, p_eex, p_den, p_h, p_x2);

    // ---- fused bias+relu(x2) + sequence build ----
    gat2_finish<<<blk_nd, TB>>>(p_x2, gat2_b, p_hx1, cls, pos, p_seq, p_hseq);

    // ---- transformer ----
    const int nwb_attn = (N_NODES * 4 * 32 + TB - 1) / TB;
    const int blk_ln   = (SEQROWS + 7) / 8;

    for (int l = 0; l < 2; l++) {
        const __half* Wq   = p_hw + OQKV + (size_t)l * 768 * 256;
        const float*  bq   = bqkv + (size_t)l * 768;
        const __half* Wo_l = p_hw + OWO + (size_t)l * 256 * 256;
        const float*  bo_l = bo + (size_t)l * 256;
        const __half* W1   = p_hw + OFF1 + (size_t)l * 1024 * 256;
        const float*  b1   = bff1 + (size_t)l * 1024;
        const __half* W2   = p_hw + OFF2 + (size_t)l * 256 * 1024;
        const float*  b2   = bff2 + (size_t)l * 256;

        launch_gemm<true, true, false>(p_hseq, Wq, bq, p_hqkv, SEQROWS, 768, 256);
        mha_attn<<<nwb_attn, TB>>>(p_hqkv, p_hattn);
        launch_gemm<false, true, false>(p_hattn, Wo_l, bo_l, p_big1, SEQROWS, 256, 256);
        ln_res<<<blk_ln, TB>>>(p_seq, p_big1, ln1_g + l * 256, ln1_b + l * 256, p_hseq, SEQROWS);
        launch_gemm<true, true, true>(p_hseq, W1, b1, p_hff, SEQROWS, 1024, 256);
        launch_gemm<false, true, false>(p_hff, W2, b2, p_big1, SEQROWS, 256, 1024);
        ln_res<<<blk_ln, TB>>>(p_seq, p_big1, ln2_g + l * 256, ln2_b + l * 256, p_hseq, SEQROWS);
    }

    ln_out<<<(N_NODES + 7) / 8, TB>>>(p_seq, norm_g, norm_b, out);
}

// round 15
// speedup vs baseline: 1.5964x; 1.0744x over previous
#include <cuda_runtime.h>
#include <cuda_fp16.h>
#include <cstdint>

#define N_NODES 50000
#define N_EDGES 320000
#define N_E2    370000
#define DIM     256
#define DIN_    128
#define SEQROWS (3*N_NODES)
#define SCANB   512
#define NSCANB  ((N_NODES + SCANB - 1) / SCANB)   // 98

// ---------------- fp32 scratch ----------------
__device__ float    g_h   [N_NODES*DIM];
__device__ float    g_x2  [N_NODES*DIM];
__device__ float    g_ssrc[N_NODES];
__device__ float    g_sdst[N_NODES];
__device__ float    g_seq [SEQROWS*DIM];
__device__ float    g_big1[(size_t)SEQROWS*256];

// ---------------- CSR scratch ----------------
__device__ int g_cnt [N_NODES];
__device__ int g_cur [N_NODES];
__device__ int g_off [N_NODES + 1];
__device__ int g_bsum[NSCANB];
__device__ int g_bbase[NSCANB];
__device__ int g_csrc[N_E2];

// ---------------- fp16 scratch ----------------
__device__ __half g_hx  [N_NODES*DIN_];
__device__ __half g_hx1 [N_NODES*DIM];
__device__ __half g_hseq[SEQROWS*DIM];
__device__ __half g_hattn[SEQROWS*DIM];
__device__ __half g_hqkv[(size_t)SEQROWS*768];
__device__ __half g_hff [(size_t)SEQROWS*1024];
// packed half weights
#define OG1  0
#define OG2  (OG1 + 256*128)
#define OQKV (OG2 + 256*256)
#define OWO  (OQKV + 2*768*256)
#define OFF1 (OWO + 2*256*256)
#define OFF2 (OFF1 + 2*1024*256)
#define HWTOT (OFF2 + 2*256*1024)
__device__ __half g_hw[HWTOT];

__device__ __forceinline__ float warp_sum(float v) {
#pragma unroll
    for (int o = 16; o; o >>= 1) v += __shfl_xor_sync(0xffffffffu, v, o);
    return v;
}
__device__ __forceinline__ uint32_t smem_u32(const void* p) {
    uint32_t a;
    asm("{ .reg .u64 t; cvta.to.shared.u64 t, %1; cvt.u32.u64 %0, t; }" : "=r"(a) : "l"(p));
    return a;
}
__device__ __forceinline__ uint32_t packh2(float x, float y) {
    uint32_t r;
    asm("cvt.rn.f16x2.f32 %0, %1, %2;" : "=r"(r) : "f"(y), "f"(x));
    return r;
}

// ---------------- f32 -> f16 convert ----------------
__global__ void cvt_f2h(const float* __restrict__ s, __half* __restrict__ d, int n)
{
    const int i = (blockIdx.x * blockDim.x + threadIdx.x) * 4;
    if (i >= n) return;
    float4 v = *(const float4*)(s + i);
    uint32_t* o = (uint32_t*)(d + i);
    o[0] = packh2(v.x, v.y);
    o[1] = packh2(v.z, v.w);
}

// ---------------- CSR build ----------------
__global__ void csr_zero(int* __restrict__ cnt, int* __restrict__ cur)
{
    const int i = blockIdx.x * blockDim.x + threadIdx.x;
    if (i < N_NODES) { cnt[i] = 0; cur[i] = 0; }
}
__global__ void csr_count(const int* __restrict__ ei, int* __restrict__ cnt)
{
    const int k = blockIdx.x * blockDim.x + threadIdx.x;
    if (k >= N_E2) return;
    const int d = (k < N_EDGES) ? ei[N_EDGES + k] : (k - N_EDGES);
    atomicAdd(&cnt[d], 1);
}
__global__ void csr_scan_block(const int* __restrict__ cnt, int* __restrict__ off,
                               int* __restrict__ bsum)
{
    __shared__ int sm[SCANB];
    const int tid = threadIdx.x;
    const int i = blockIdx.x * SCANB + tid;
    const int v = (i < N_NODES) ? cnt[i] : 0;
    sm[tid] = v;
    __syncthreads();
    for (int o = 1; o < SCANB; o <<= 1) {
        int t = (tid >= o) ? sm[tid - o] : 0;
        __syncthreads();
        sm[tid] += t;
        __syncthreads();
    }
    if (i < N_NODES) off[i] = sm[tid] - v;      // exclusive within block
    if (tid == SCANB - 1) bsum[blockIdx.x] = sm[tid];
}
__global__ void csr_scan_tops(const int* __restrict__ bsum, int* __restrict__ bbase)
{
    if (threadIdx.x == 0) {
        int acc = 0;
        for (int b = 0; b < NSCANB; b++) { bbase[b] = acc; acc += bsum[b]; }
    }
}
__global__ void csr_add_base(int* __restrict__ off, const int* __restrict__ bbase)
{
    const int i = blockIdx.x * blockDim.x + threadIdx.x;
    if (i < N_NODES) off[i] += bbase[i / SCANB];
    if (i == 0) off[N_NODES] = N_E2;
}
__global__ void csr_fill(const int* __restrict__ ei, const int* __restrict__ off,
                         int* __restrict__ cur, int* __restrict__ csrc)
{
    const int k = blockIdx.x * blockDim.x + threadIdx.x;
    if (k >= N_E2) return;
    const int s = (k < N_EDGES) ? ei[k] : (k - N_EDGES);
    const int d = (k < N_EDGES) ? ei[N_EDGES + k] : (k - N_EDGES);
    const int slot = atomicAdd(&cur[d], 1);
    csrc[off[d] + slot] = s;
}

// ============== fp16 cp.async GEMM: C[M,Nn] = A[M,K] @ W[Nn,K]^T ==============
#define TILEB 16384
#define BUFB  (2*TILEB)
#define GSMEM (3*BUFB)              // 98304

__device__ __forceinline__ void cp16(uint32_t s, const void* g) {
    asm volatile("cp.async.cg.shared.global [%0], [%1], 16;" :: "r"(s), "l"(g));
}
__device__ __forceinline__ void ldsm4(uint32_t& r0, uint32_t& r1, uint32_t& r2, uint32_t& r3,
                                      uint32_t addr) {
    asm volatile("ldmatrix.sync.aligned.m8n8.x4.shared.b16 {%0,%1,%2,%3}, [%4];"
                 : "=r"(r0), "=r"(r1), "=r"(r2), "=r"(r3) : "r"(addr));
}
__device__ __forceinline__ void mma_f16(float* c, uint32_t a0, uint32_t a1,
                                        uint32_t a2, uint32_t a3,
                                        uint32_t b0, uint32_t b1) {
    asm volatile(
        "mma.sync.aligned.m16n8k16.row.col.f32.f16.f16.f32 "
        "{%0,%1,%2,%3}, {%4,%5,%6,%7}, {%8,%9}, {%0,%1,%2,%3};"
        : "+f"(c[0]), "+f"(c[1]), "+f"(c[2]), "+f"(c[3])
        : "r"(a0), "r"(a1), "r"(a2), "r"(a3), "r"(b0), "r"(b1));
}

template<bool OUT_HALF, bool BIAS, bool RELU>
__global__ void __launch_bounds__(256, 2) hgemm(
    const __half* __restrict__ A, const __half* __restrict__ W,
    const float* __restrict__ bias, void* __restrict__ Cv,
    int M, int Nn, int K)
{
    extern __shared__ char smraw[];
    const int tid  = threadIdx.x;
    const int lane = tid & 31;
    const int wid  = tid >> 5;
    const int warp_m = wid >> 2;
    const int warp_n = wid & 3;
    const int g  = lane >> 2;
    const int cl = lane & 3;
    const int bm0 = blockIdx.x * 128;
    const int bn0 = blockIdx.y * 128;
    const uint32_t smem_byte = smem_u32(smraw);

    float acc[4][4][4];
#pragma unroll
    for (int mi = 0; mi < 4; mi++)
#pragma unroll
        for (int ni = 0; ni < 4; ni++)
#pragma unroll
            for (int c = 0; c < 4; c++) acc[mi][ni][c] = 0.f;

    const int stages = K >> 6;
    const int ld_r = tid >> 3;
    const int ld_c = tid & 7;

    auto issue = [&](int s) {
        const uint32_t abase = smem_byte + (uint32_t)(s % 3) * BUFB;
        const uint32_t bbase = abase + TILEB;
        const int k0 = s << 6;
#pragma unroll
        for (int i = 0; i < 4; i++) {
            const int r = ld_r + 32 * i;
            const uint32_t sw = (uint32_t)((ld_c ^ (r & 7)) << 4);
            int ar = bm0 + r; if (ar > M - 1) ar = M - 1;
            cp16(abase + (uint32_t)r * 128 + sw, A + (size_t)ar * K + k0 + ld_c * 8);
            cp16(bbase + (uint32_t)r * 128 + sw, W + (size_t)(bn0 + r) * K + k0 + ld_c * 8);
        }
        asm volatile("cp.async.commit_group;" ::: "memory");
    };

    issue(0);
    if (stages > 1) issue(1);

    for (int s = 0; s < stages; s++) {
        if (s + 1 < stages) {
            asm volatile("cp.async.wait_group 1;" ::: "memory");
        } else {
            asm volatile("cp.async.wait_group 0;" ::: "memory");
        }
        __syncthreads();
        if (s + 2 < stages) issue(s + 2);

        const uint32_t Ab = smem_byte + (uint32_t)(s % 3) * BUFB;
        const uint32_t Bb = Ab + TILEB;
        const int row_a = warp_m * 64 + (lane & 15);
        const int ca = lane >> 4;
        const int row_b0 = warp_n * 32 + (lane & 7) + ((lane >> 4) & 1) * 8;
        const int cb = (lane >> 3) & 1;

#pragma unroll
        for (int kq = 0; kq < 4; kq++) {
            const int kb = kq * 2;
            uint32_t afr[4][4];
            uint32_t bfr[4][2];
            const uint32_t sw_a = (uint32_t)(((kb + ca) ^ (lane & 7)) << 4);
#pragma unroll
            for (int mi = 0; mi < 4; mi++)
                ldsm4(afr[mi][0], afr[mi][1], afr[mi][2], afr[mi][3],
                      Ab + (uint32_t)(row_a + mi * 16) * 128 + sw_a);
            const uint32_t sw_b = (uint32_t)(((kb + cb) ^ (lane & 7)) << 4);
#pragma unroll
            for (int p = 0; p < 2; p++)
                ldsm4(bfr[2*p][0], bfr[2*p][1], bfr[2*p+1][0], bfr[2*p+1][1],
                      Bb + (uint32_t)(row_b0 + p * 16) * 128 + sw_b);
#pragma unroll
            for (int mi = 0; mi < 4; mi++)
#pragma unroll
                for (int ni = 0; ni < 4; ni++)
                    mma_f16(acc[mi][ni], afr[mi][0], afr[mi][1], afr[mi][2], afr[mi][3],
                            bfr[ni][0], bfr[ni][1]);
        }
    }

    // epilogue
#pragma unroll
    for (int mi = 0; mi < 4; mi++) {
        const int r0 = bm0 + warp_m * 64 + mi * 16 + g;
#pragma unroll
        for (int ni = 0; ni < 4; ni++) {
            const int col = bn0 + warp_n * 32 + ni * 8 + 2 * cl;
            float bx = 0.f, by = 0.f;
            if (BIAS) { bx = __ldg(bias + col); by = __ldg(bias + col + 1); }
            float2 v0, v1;
            v0.x = acc[mi][ni][0] + bx; v0.y = acc[mi][ni][1] + by;
            v1.x = acc[mi][ni][2] + bx; v1.y = acc[mi][ni][3] + by;
            if (RELU) {
                v0.x = fmaxf(v0.x, 0.f); v0.y = fmaxf(v0.y, 0.f);
                v1.x = fmaxf(v1.x, 0.f); v1.y = fmaxf(v1.y, 0.f);
            }
            if (OUT_HALF) {
                __half* Ch = (__half*)Cv;
                if (r0 < M)     *(uint32_t*)(Ch + (size_t)r0 * Nn + col)       = packh2(v0.x, v0.y);
                if (r0 + 8 < M) *(uint32_t*)(Ch + (size_t)(r0 + 8) * Nn + col) = packh2(v1.x, v1.y);
            } else {
                float* C = (float*)Cv;
                if (r0 < M)     *(float2*)(C + (size_t)r0 * Nn + col)       = v0;
                if (r0 + 8 < M) *(float2*)(C + (size_t)(r0 + 8) * Nn + col) = v1;
            }
        }
    }
}

// ---------------- GAT ----------------
__global__ void gat_scores(const float* __restrict__ h,
                           const float* __restrict__ asrc, const float* __restrict__ adst,
                           float* __restrict__ ssrc, float* __restrict__ sdst)
{
    const int gw = (int)(((size_t)blockIdx.x * blockDim.x + threadIdx.x) >> 5);
    const int lane = threadIdx.x & 31;
    if (gw >= N_NODES) return;
    const float4* hp = (const float4*)(h + (size_t)gw * DIM);
    float s1 = 0.f, s2 = 0.f;
#pragma unroll
    for (int i = 0; i < 2; i++) {
        float4 hv = hp[lane + 32 * i];
        float4 a1 = ((const float4*)asrc)[lane + 32 * i];
        float4 a2 = ((const float4*)adst)[lane + 32 * i];
        s1 += hv.x*a1.x + hv.y*a1.y + hv.z*a1.z + hv.w*a1.w;
        s2 += hv.x*a2.x + hv.y*a2.y + hv.z*a2.z + hv.w*a2.w;
    }
    s1 = warp_sum(s1); s2 = warp_sum(s2);
    if (lane == 0) { ssrc[gw] = s1; sdst[gw] = s2; }
}

// node-centric GAT aggregation: warp per node, no atomics.
// L1: out = half(relu(agg + bias));  else: out = raw fp32 agg.
template<bool L1>
__global__ void gat_node(const float* __restrict__ h,
                         const float* __restrict__ ssrc, const float* __restrict__ sdst,
                         const int* __restrict__ off, const int* __restrict__ csrc,
                         const float* __restrict__ bias,
                         __half* __restrict__ outh, float* __restrict__ outf)
{
    const int v = (int)(((size_t)blockIdx.x * blockDim.x + threadIdx.x) >> 5);
    const int lane = threadIdx.x & 31;
    if (v >= N_NODES) return;
    const int o0 = off[v];
    const int deg = off[v + 1] - o0;
    const float sd = sdst[v];

    float m = -1e30f;
    for (int i = lane; i < deg; i += 32) {
        const int s = csrc[o0 + i];
        float e = ssrc[s] + sd;
        e = (e >= 0.f) ? e : 0.2f * e;
        m = fmaxf(m, e);
    }
#pragma unroll
    for (int o = 16; o; o >>= 1) m = fmaxf(m, __shfl_xor_sync(0xffffffffu, m, o));

    float ss = 0.f;
    for (int i = lane; i < deg; i += 32) {
        const int s = csrc[o0 + i];
        float e = ssrc[s] + sd;
        e = (e >= 0.f) ? e : 0.2f * e;
        ss += expf(e - m);
    }
    ss = warp_sum(ss);
    const float inv = 1.f / ss;

    float4 a0 = make_float4(0.f, 0.f, 0.f, 0.f);
    float4 a1 = make_float4(0.f, 0.f, 0.f, 0.f);
    for (int i = 0; i < deg; i++) {
        const int s = csrc[o0 + i];            // warp-uniform broadcast
        float e = ssrc[s] + sd;
        e = (e >= 0.f) ? e : 0.2f * e;
        const float a = expf(e - m) * inv;
        const float4* hp = (const float4*)(h + (size_t)s * DIM);
        const float4 u0 = hp[lane], u1 = hp[lane + 32];
        a0.x += a * u0.x; a0.y += a * u0.y; a0.z += a * u0.z; a0.w += a * u0.w;
        a1.x += a * u1.x; a1.y += a * u1.y; a1.z += a * u1.z; a1.w += a * u1.w;
    }

    if (L1) {
        const float4 b0 = ((const float4*)bias)[lane];
        const float4 b1 = ((const float4*)bias)[lane + 32];
        a0.x = fmaxf(a0.x + b0.x, 0.f); a0.y = fmaxf(a0.y + b0.y, 0.f);
        a0.z = fmaxf(a0.z + b0.z, 0.f); a0.w = fmaxf(a0.w + b0.w, 0.f);
        a1.x = fmaxf(a1.x + b1.x, 0.f); a1.y = fmaxf(a1.y + b1.y, 0.f);
        a1.z = fmaxf(a1.z + b1.z, 0.f); a1.w = fmaxf(a1.w + b1.w, 0.f);
        uint2* hp = (uint2*)(outh + (size_t)v * DIM);
        uint2 h0, h1;
        h0.x = packh2(a0.x, a0.y); h0.y = packh2(a0.z, a0.w);
        h1.x = packh2(a1.x, a1.y); h1.y = packh2(a1.z, a1.w);
        hp[lane] = h0; hp[lane + 32] = h1;
    } else {
        float4* op = (float4*)(outf + (size_t)v * DIM);
        op[lane] = a0; op[lane + 32] = a1;
    }
}

// fused: x2 = relu(x2_acc + b); seq/hseq build for all 3 tokens (x1 read as half)
__global__ void gat2_finish(const float* __restrict__ x2acc, const float* __restrict__ b,
                            const __half* __restrict__ x1h,
                            const float* __restrict__ cls, const float* __restrict__ pos,
                            float* __restrict__ seq, __half* __restrict__ seqh)
{
    const int idx = blockIdx.x * blockDim.x + threadIdx.x;
    if (idx >= N_NODES * DIM) return;
    const int d = idx & (DIM - 1);
    const size_t bq = (size_t)(idx >> 8) * 3 * DIM;
    const float v2r = fmaxf(x2acc[idx] + b[d], 0.f);
    const float v0 = cls[d] + pos[d];
    const float v1 = __half2float(x1h[idx]) + pos[DIM + d];
    const float v2 = v2r + pos[2 * DIM + d];
    seq[bq + d] = v0;           seqh[bq + d] = __float2half(v0);
    seq[bq + DIM + d] = v1;     seqh[bq + DIM + d] = __float2half(v1);
    seq[bq + 2*DIM + d] = v2;   seqh[bq + 2*DIM + d] = __float2half(v2);
}

// attention: warp per (node, head); half2 vectorized
__global__ void mha_attn(const __half* __restrict__ qkv, __half* __restrict__ o)
{
    const int gw = (int)(((size_t)blockIdx.x * blockDim.x + threadIdx.x) >> 5);
    const int lane = threadIdx.x & 31;
    if (gw >= N_NODES * 4) return;
    const int n = gw >> 2, h = gw & 3;
    const __half* base = qkv + (size_t)n * (3 * 768) + h * 64 + 2 * lane;
    float2 q[3], k[3], v[3];
#pragma unroll
    for (int i = 0; i < 3; i++) {
        q[i] = __half22float2(*(const __half2*)(base + i * 768));
        k[i] = __half22float2(*(const __half2*)(base + i * 768 + 256));
        v[i] = __half22float2(*(const __half2*)(base + i * 768 + 512));
    }
    float lg[3][3];
#pragma unroll
    for (int i = 0; i < 3; i++)
#pragma unroll
        for (int j = 0; j < 3; j++)
            lg[i][j] = warp_sum(q[i].x * k[j].x + q[i].y * k[j].y) * 0.125f;
    __half* ob = o + (size_t)n * 768 + h * 64 + 2 * lane;
#pragma unroll
    for (int i = 0; i < 3; i++) {
        const float m = fmaxf(lg[i][0], fmaxf(lg[i][1], lg[i][2]));
        const float e0 = expf(lg[i][0] - m), e1 = expf(lg[i][1] - m), e2 = expf(lg[i][2] - m);
        const float inv = 1.f / (e0 + e1 + e2);
        const float a0 = e0 * inv, a1 = e1 * inv, a2 = e2 * inv;
        const float o0 = a0*v[0].x + a1*v[1].x + a2*v[2].x;
        const float o1 = a0*v[0].y + a1*v[1].y + a2*v[2].y;
        *(uint32_t*)(ob + i * 256) = packh2(o0, o1);
    }
}

__global__ void ln_res(float* __restrict__ x, const float* __restrict__ delta,
                       const float* __restrict__ g, const float* __restrict__ b,
                       __half* __restrict__ xh, int rows)
{
    const int row = blockIdx.x * 8 + (threadIdx.x >> 5);
    const int lane = threadIdx.x & 31;
    if (row >= rows) return;
    float4* xp = (float4*)(x + (size_t)row * DIM);
    const float4* dp = (const float4*)(delta + (size_t)row * DIM);
    float4 v0 = xp[lane], v1 = xp[lane + 32];
    float4 d0 = dp[lane], d1 = dp[lane + 32];
    v0.x += d0.x; v0.y += d0.y; v0.z += d0.z; v0.w += d0.w;
    v1.x += d1.x; v1.y += d1.y; v1.z += d1.z; v1.w += d1.w;
    float s  = v0.x + v0.y + v0.z + v0.w + v1.x + v1.y + v1.z + v1.w;
    float s2 = v0.x*v0.x + v0.y*v0.y + v0.z*v0.z + v0.w*v0.w
             + v1.x*v1.x + v1.y*v1.y + v1.z*v1.z + v1.w*v1.w;
    s = warp_sum(s); s2 = warp_sum(s2);
    const float mean = s * (1.f / DIM);
    const float var  = s2 * (1.f / DIM) - mean * mean;
    const float inv = rsqrtf(var + 1e-5f);
    float4 g0 = ((const float4*)g)[lane], g1 = ((const float4*)g)[lane + 32];
    float4 b0 = ((const float4*)b)[lane], b1 = ((const float4*)b)[lane + 32];
    v0.x = (v0.x - mean) * inv * g0.x + b0.x; v0.y = (v0.y - mean) * inv * g0.y + b0.y;
    v0.z = (v0.z - mean) * inv * g0.z + b0.z; v0.w = (v0.w - mean) * inv * g0.w + b0.w;
    v1.x = (v1.x - mean) * inv * g1.x + b1.x; v1.y = (v1.y - mean) * inv * g1.y + b1.y;
    v1.z = (v1.z - mean) * inv * g1.z + b1.z; v1.w = (v1.w - mean) * inv * g1.w + b1.w;
    xp[lane] = v0; xp[lane + 32] = v1;
    uint2* hp = (uint2*)(xh + (size_t)row * DIM);
    uint2 h0, h1;
    h0.x = packh2(v0.x, v0.y); h0.y = packh2(v0.z, v0.w);
    h1.x = packh2(v1.x, v1.y); h1.y = packh2(v1.z, v1.w);
    hp[lane] = h0; hp[lane + 32] = h1;
}

__global__ void ln_out(const float* __restrict__ seq,
                       const float* __restrict__ g, const float* __restrict__ b,
                       float* __restrict__ out)
{
    const int row = blockIdx.x * 8 + (threadIdx.x >> 5);
    const int lane = threadIdx.x & 31;
    if (row >= N_NODES) return;
    const float4* xp = (const float4*)(seq + (size_t)row * 768);
    float4 v0 = xp[lane], v1 = xp[lane + 32];
    float s  = v0.x + v0.y + v0.z + v0.w + v1.x + v1.y + v1.z + v1.w;
    float s2 = v0.x*v0.x + v0.y*v0.y + v0.z*v0.z + v0.w*v0.w
             + v1.x*v1.x + v1.y*v1.y + v1.z*v1.z + v1.w*v1.w;
    s = warp_sum(s); s2 = warp_sum(s2);
    const float mean = s * (1.f / DIM);
    const float var  = s2 * (1.f / DIM) - mean * mean;
    const float inv = rsqrtf(var + 1e-5f);
    float4 g0 = ((const float4*)g)[lane], g1 = ((const float4*)g)[lane + 32];
    float4 b0 = ((const float4*)b)[lane], b1 = ((const float4*)b)[lane + 32];
    v0.x = (v0.x - mean) * inv * g0.x + b0.x; v0.y = (v0.y - mean) * inv * g0.y + b0.y;
    v0.z = (v0.z - mean) * inv * g0.z + b0.z; v0.w = (v0.w - mean) * inv * g0.w + b0.w;
    v1.x = (v1.x - mean) * inv * g1.x + b1.x; v1.y = (v1.y - mean) * inv * g1.y + b1.y;
    v1.z = (v1.z - mean) * inv * g1.z + b1.z; v1.w = (v1.w - mean) * inv * g1.w + b1.w;
    float4* op = (float4*)(out + (size_t)row * DIM);
    op[lane] = v0; op[lane + 32] = v1;
}

// ---------------- host ----------------
static void* symaddr(const void* sym) {
    void* p = nullptr;
    cudaGetSymbolAddress(&p, sym);
    return p;
}

template<bool OUT_HALF, bool BIAS, bool RELU>
static void launch_gemm(const __half* A, const __half* W, const float* bias, void* C,
                        int M, int Nn, int K)
{
    cudaFuncSetAttribute(hgemm<OUT_HALF, BIAS, RELU>,
                         cudaFuncAttributeMaxDynamicSharedMemorySize, GSMEM);
    dim3 grid((M + 127) / 128, Nn / 128);
    hgemm<OUT_HALF, BIAS, RELU><<<grid, 256, GSMEM>>>(A, W, bias, C, M, Nn, K);
}

static void cvt(const float* s, __half* d, int n) {
    cvt_f2h<<<(n / 4 + 255) / 256, 256>>>(s, d, n);
}

extern "C" void kernel_launch(void* const* d_in, const int* in_sizes, int n_in,
                              void* d_out, int out_size)
{
    (void)in_sizes; (void)n_in; (void)out_size;
    const float* x         = (const float*)d_in[0];
    const int*   ei        = (const int*)  d_in[1];
    const float* gat1_W    = (const float*)d_in[2];
    const float* gat1_b    = (const float*)d_in[3];
    const float* gat1_asrc = (const float*)d_in[4];
    const float* gat1_adst = (const float*)d_in[5];
    const float* gat2_W    = (const float*)d_in[6];
    const float* gat2_b    = (const float*)d_in[7];
    const float* gat2_asrc = (const float*)d_in[8];
    const float* gat2_adst = (const float*)d_in[9];
    const float* cls       = (const float*)d_in[10];
    const float* pos       = (const float*)d_in[11];
    const float* Wqkv      = (const float*)d_in[12];
    const float* bqkv      = (const float*)d_in[13];
    const float* Wo        = (const float*)d_in[14];
    const float* bo        = (const float*)d_in[15];
    const float* ln1_g     = (const float*)d_in[16];
    const float* ln1_b     = (const float*)d_in[17];
    const float* ln2_g     = (const float*)d_in[18];
    const float* ln2_b     = (const float*)d_in[19];
    const float* Wff1      = (const float*)d_in[20];
    const float* bff1      = (const float*)d_in[21];
    const float* Wff2      = (const float*)d_in[22];
    const float* bff2      = (const float*)d_in[23];
    const float* norm_g    = (const float*)d_in[24];
    const float* norm_b    = (const float*)d_in[25];
    float* out = (float*)d_out;

    float*    p_h    = (float*)symaddr(g_h);
    float*    p_x2   = (float*)symaddr(g_x2);
    float*    p_ssrc = (float*)symaddr(g_ssrc);
    float*    p_sdst = (float*)symaddr(g_sdst);
    float*    p_seq  = (float*)symaddr(g_seq);
    float*    p_big1 = (float*)symaddr(g_big1);
    int*      p_cnt  = (int*)symaddr(g_cnt);
    int*      p_cur  = (int*)symaddr(g_cur);
    int*      p_off  = (int*)symaddr(g_off);
    int*      p_bsum = (int*)symaddr(g_bsum);
    int*      p_bbase= (int*)symaddr(g_bbase);
    int*      p_csrc = (int*)symaddr(g_csrc);
    __half*   p_hx   = (__half*)symaddr(g_hx);
    __half*   p_hx1  = (__half*)symaddr(g_hx1);
    __half*   p_hseq = (__half*)symaddr(g_hseq);
    __half*   p_hattn= (__half*)symaddr(g_hattn);
    __half*   p_hqkv = (__half*)symaddr(g_hqkv);
    __half*   p_hff  = (__half*)symaddr(g_hff);
    __half*   p_hw   = (__half*)symaddr(g_hw);

    // ---- one-time converts ----
    cvt(x, p_hx, N_NODES * DIN_);
    cvt(gat1_W, p_hw + OG1, 256 * 128);
    cvt(gat2_W, p_hw + OG2, 256 * 256);
    cvt(Wqkv,   p_hw + OQKV, 2 * 768 * 256);
    cvt(Wo,     p_hw + OWO,  2 * 256 * 256);
    cvt(Wff1,   p_hw + OFF1, 2 * 1024 * 256);
    cvt(Wff2,   p_hw + OFF2, 2 * 256 * 1024);

    const int TB = 256;
    const int nwb_nodes = (N_NODES * 32 + TB - 1) / TB;
    const int blk_nd    = (N_NODES * DIM + TB - 1) / TB;
    const int blk_e     = (N_E2 + TB - 1) / TB;
    const int blk_n     = (N_NODES + TB - 1) / TB;

    // ---- CSR build (once) ----
    csr_zero<<<blk_n, TB>>>(p_cnt, p_cur);
    csr_count<<<blk_e, TB>>>(ei, p_cnt);
    csr_scan_block<<<NSCANB, SCANB>>>(p_cnt, p_off, p_bsum);
    csr_scan_tops<<<1, 32>>>(p_bsum, p_bbase);
    csr_add_base<<<blk_n, TB>>>(p_off, p_bbase);
    csr_fill<<<blk_e, TB>>>(ei, p_off, p_cur, p_csrc);

    // ---- GAT layer 1 ----
    launch_gemm<false, false, false>(p_hx, p_hw + OG1, nullptr, p_h, N_NODES, DIM, DIN_);
    gat_scores<<<nwb_nodes, TB>>>(p_h, gat1_asrc, gat1_adst, p_ssrc, p_sdst);
    gat_node<true><<<nwb_nodes, TB>>>(p_h, p_ssrc, p_sdst, p_off, p_csrc, gat1_b, p_hx1, nullptr);

    // ---- GAT layer 2 ----
    launch_gemm<false, false, false>(p_hx1, p_hw + OG2, nullptr, p_h, N_NODES, DIM, DIM);
    gat_scores<<<nwb_nodes, TB>>>(p_h, gat2_asrc, gat2_adst, p_ssrc, p_sdst);
    gat_node<false><<<nwb_nodes, TB>>>(p_h, p_ssrc, p_sdst, p_off, p_csrc, nullptr, nullptr, p_x2);

    // ---- fused bias+relu(x2) + sequence build ----
    gat2_finish<<<blk_nd, TB>>>(p_x2, gat2_b, p_hx1, cls, pos, p_seq, p_hseq);

    // ---- transformer ----
    const int nwb_attn = (N_NODES * 4 * 32 + TB - 1) / TB;
    const int blk_ln   = (SEQROWS + 7) / 8;

    for (int l = 0; l < 2; l++) {
        const __half* Wq   = p_hw + OQKV + (size_t)l * 768 * 256;
        const float*  bq   = bqkv + (size_t)l * 768;
        const __half* Wo_l = p_hw + OWO + (size_t)l * 256 * 256;
        const float*  bo_l = bo + (size_t)l * 256;
        const __half* W1   = p_hw + OFF1 + (size_t)l * 1024 * 256;
        const float*  b1   = bff1 + (size_t)l * 1024;
        const __half* W2   = p_hw + OFF2 + (size_t)l * 256 * 1024;
        const float*  b2   = bff2 + (size_t)l * 256;

        launch_gemm<true, true, false>(p_hseq, Wq, bq, p_hqkv, SEQROWS, 768, 256);
        mha_attn<<<nwb_attn, TB>>>(p_hqkv, p_hattn);
        launch_gemm<false, true, false>(p_hattn, Wo_l, bo_l, p_big1, SEQROWS, 256, 256);
        ln_res<<<blk_ln, TB>>>(p_seq, p_big1, ln1_g + l * 256, ln1_b + l * 256, p_hseq, SEQROWS);
        launch_gemm<true, true, true>(p_hseq, W1, b1, p_hff, SEQROWS, 1024, 256);
        launch_gemm<false, true, false>(p_hff, W2, b2, p_big1, SEQROWS, 256, 1024);
        ln_res<<<blk_ln, TB>>>(p_seq, p_big1, ln2_g + l * 256, ln2_b + l * 256, p_hseq, SEQROWS);
    }

    ln_out<<<(N_NODES + 7) / 8, TB>>>(p_seq, norm_g, norm_b, out);
}